// round 11
// baseline (speedup 1.0000x reference)
#include <cuda_runtime.h>
#include <cuda_fp16.h>
#include <cstdint>

// Problem constants
#define BATCH   8
#define CIN     384
#define NPIX    3136           // 56*56
#define WWID    56
#define BP      25088          // BATCH*NPIX
#define INNER   512
#define KVOUT   1024
#define HEADS   8
#define DH      64
#define NBH     64
#define SCALE_F 0.125f
#define EPS_F   1e-5f
#define NSPLIT  7

// ---------------------------------------------------------------------------
// Scratch (device globals)
// ---------------------------------------------------------------------------
__device__ __align__(16) __half g_yq_h [(size_t)BP * CIN];   // dwconv out, q path  [n][c]
__device__ __align__(16) __half g_ykv_h[(size_t)BP * CIN];   // dwconv out, kv path [n][c]
__device__ __align__(16) __half g_q_h [(size_t)INNER * BP];  // q   [m][n] fp16
__device__ __align__(16) __half g_kv_h[(size_t)KVOUT * BP];  // k|v [m][n] fp16
__device__ __align__(16) __half g_att_h[(size_t)BP * INNER]; // attention out [n][o]
__device__ __align__(16) __half g_wq_h [INNER * CIN];        // fp16 weights
__device__ __align__(16) __half g_wkv_h[KVOUT * CIN];
__device__ __align__(16) __half g_wo_h [CIN * INNER];
__device__ float g_diag[NBH * NPIX];
__device__ float g_ktvp[NSPLIT * NBH * DH * DH];
__device__ float g_ktv [NBH * DH * DH];
__device__ float g_red[256];
__device__ float g_m0[1];

// ---------------------------------------------------------------------------
// Helpers
// ---------------------------------------------------------------------------
__device__ __forceinline__ uint32_t smem_u32(const void* p) {
    uint32_t a;
    asm("{ .reg .u64 t; cvta.to.shared.u64 t, %1; cvt.u32.u64 %0, t; }" : "=r"(a) : "l"(p));
    return a;
}
__device__ __forceinline__ void cp_async16(uint32_t dst, const void* src) {
    asm volatile("cp.async.cg.shared.global [%0], [%1], 16;" :: "r"(dst), "l"(src));
}
#define CP_COMMIT() asm volatile("cp.async.commit_group;" ::: "memory")
#define CP_WAIT(N)  asm volatile("cp.async.wait_group %0;" :: "n"(N) : "memory")

__device__ __forceinline__ void mma_f16(float* c, const uint32_t* a, const uint32_t* b) {
    asm volatile(
        "mma.sync.aligned.m16n8k16.row.col.f32.f16.f16.f32 "
        "{%0,%1,%2,%3}, {%4,%5,%6,%7}, {%8,%9}, {%0,%1,%2,%3};"
        : "+f"(c[0]), "+f"(c[1]), "+f"(c[2]), "+f"(c[3])
        : "r"(a[0]), "r"(a[1]), "r"(a[2]), "r"(a[3]), "r"(b[0]), "r"(b[1]));
}
__device__ __forceinline__ void ldsm_x4(uint32_t& r0, uint32_t& r1, uint32_t& r2, uint32_t& r3,
                                        uint32_t addr) {
    asm volatile("ldmatrix.sync.aligned.m8n8.x4.shared.b16 {%0,%1,%2,%3}, [%4];"
                 : "=r"(r0), "=r"(r1), "=r"(r2), "=r"(r3) : "r"(addr));
}

// ---------------------------------------------------------------------------
// 0) Weight conversion (fp32 -> fp16), all three weights in one launch
// ---------------------------------------------------------------------------
#define NW1 (INNER * CIN)
#define NW2 (KVOUT * CIN)
#define NW3 (CIN * INNER)
__global__ void cvt_weights_kernel(const float* __restrict__ s1, const float* __restrict__ s2,
                                   const float* __restrict__ s3)
{
    int i = blockIdx.x * 256 + threadIdx.x;
    if (i < NW1) {
        g_wq_h[i] = __float2half_rn(s1[i]);
    } else if (i < NW1 + NW2) {
        g_wkv_h[i - NW1] = __float2half_rn(s2[i - NW1]);
    } else if (i < NW1 + NW2 + NW3) {
        g_wo_h[i - NW1 - NW2] = __float2half_rn(s3[i - NW1 - NW2]);
    }
}

// ---------------------------------------------------------------------------
// 1) Depthwise 3x3 conv + BN, SMEM halo tiling, output [n][c] fp16.
//    Block = (row-strip of 8, channel-group of 8, batch).
// ---------------------------------------------------------------------------
__global__ void __launch_bounds__(256) dwconv_bn_kernel(
    const float* __restrict__ x,
    const float* __restrict__ w1, const float* __restrict__ g1, const float* __restrict__ b1,
    const float* __restrict__ m1, const float* __restrict__ v1,
    const float* __restrict__ w2, const float* __restrict__ g2, const float* __restrict__ b2,
    const float* __restrict__ m2, const float* __restrict__ v2)
{
    __shared__ float sx[8 * 10 * 58];      // 8 ch x 10 rows x 58 cols (halo)
    __shared__ float sw1[8][9], sw2[8][9];
    __shared__ float sbn[8][4];            // inv1, add1, inv2, add2

    int rs = blockIdx.x;                   // 0..6 row strip
    int cg = blockIdx.y;                   // 0..47 channel group
    int b  = blockIdx.z;
    int c0 = cg * 8;
    int tid = threadIdx.x;

    if (tid < 8) {
        int c = c0 + tid;
        float inv1 = g1[c] * rsqrtf(v1[c] + EPS_F);
        float inv2 = g2[c] * rsqrtf(v2[c] + EPS_F);
        sbn[tid][0] = inv1; sbn[tid][1] = b1[c] - m1[c] * inv1;
        sbn[tid][2] = inv2; sbn[tid][3] = b2[c] - m2[c] * inv2;
    }
    if (tid < 72)               sw1[tid / 9][tid % 9] = w1[(c0 + tid / 9) * 9 + tid % 9];
    else if (tid < 144) { int t = tid - 72; sw2[t / 9][t % 9] = w2[(c0 + t / 9) * 9 + t % 9]; }

    int h_base = rs * 8 - 1;
    for (int idx = tid; idx < 8 * 10 * 58; idx += 256) {
        int ch  = idx / 580;
        int rem = idx - ch * 580;
        int r   = rem / 58;
        int cc  = rem - r * 58;
        int h = h_base + r, w = cc - 1;
        float v = 0.f;
        if (h >= 0 && h < WWID && w >= 0 && w < WWID)
            v = x[((size_t)(b * CIN + c0 + ch)) * NPIX + h * WWID + w];
        sx[idx] = v;
    }
    __syncthreads();

    for (int px = tid; px < 448; px += 256) {
        int r  = px / WWID;                 // 0..7
        int cc = px - r * WWID;             // 0..55
        int n = b * NPIX + (rs * 8 + r) * WWID + cc;
        __half o1[8], o2[8];
#pragma unroll
        for (int ch = 0; ch < 8; ch++) {
            const float* s = sx + ch * 580 + r * 58 + cc;
            float a1 = 0.f, a2 = 0.f;
#pragma unroll
            for (int dr = 0; dr < 3; dr++) {
#pragma unroll
                for (int dc = 0; dc < 3; dc++) {
                    float xv = s[dr * 58 + dc];
                    a1 += xv * sw1[ch][dr * 3 + dc];
                    a2 += xv * sw2[ch][dr * 3 + dc];
                }
            }
            o1[ch] = __float2half_rn(a1 * sbn[ch][0] + sbn[ch][1]);
            o2[ch] = __float2half_rn(a2 * sbn[ch][2] + sbn[ch][3]);
        }
        size_t base = (size_t)n * CIN + c0;
        *(uint4*)(g_yq_h  + base) = *(uint4*)o1;    // 8 halves = 16B
        *(uint4*)(g_ykv_h + base) = *(uint4*)o2;
    }
}

// ---------------------------------------------------------------------------
// 2) fp16 mma.sync GEMM, 3-stage cp.async pipeline, ldmatrix fragments.
//    C[m][n] = sum_k A[m][k] * B[n][k], fp32 accum.
//    MODE 0: fp16 output to C[m*BP + n].  MODE 1: fp32 NCHW scatter + bias.
// ---------------------------------------------------------------------------
#define KTILE   32                        // halves per k-tile
#define SROW_H  40                        // halves per SMEM row (80B stride)
#define TILE_H  (128 * SROW_H)            // halves per operand tile
#define NSTAGE  3
#define STAGE_BYTES (2 * TILE_H * 2)      // A+B per stage
#define SMEM_GEMM_BYTES (NSTAGE * STAGE_BYTES)

template<int MODE>
__global__ void __launch_bounds__(256, 2) gemm_f16(
    const __half* __restrict__ A, const __half* __restrict__ Bm,
    void* __restrict__ Cv, int Kd, const float* __restrict__ bias)
{
    extern __shared__ __half smem[];
    int tid = threadIdx.x;
    int wid = tid >> 5;
    int lane = tid & 31;
    int grp = lane >> 2;          // 0..7
    int qid = lane & 3;           // 0..3
    int warp_m = wid & 1;
    int warp_n = wid >> 1;

    int n0 = blockIdx.x * 128;
    int m0 = blockIdx.y * 128;
    int KT = Kd / KTILE;

    uint32_t smem_b = smem_u32(smem);

    auto load_tile = [&](int kt, int stage) {
        int k0 = kt * KTILE;
        uint32_t dA = smem_b + (uint32_t)stage * STAGE_BYTES;
        uint32_t dB = dA + TILE_H * 2;
#pragma unroll
        for (int i = 0; i < 2; i++) {
            int idx = tid + i * 256;
            int row = idx >> 2, q = idx & 3;
            cp_async16(dA + (uint32_t)(row * SROW_H + q * 8) * 2,
                       A + (size_t)(m0 + row) * Kd + k0 + q * 8);
        }
#pragma unroll
        for (int i = 0; i < 2; i++) {
            int idx = tid + i * 256;
            int row = idx >> 2, q = idx & 3;
            cp_async16(dB + (uint32_t)(row * SROW_H + q * 8) * 2,
                       Bm + (size_t)(n0 + row) * Kd + k0 + q * 8);
        }
    };

    float acc[4][4][4];
#pragma unroll
    for (int mt = 0; mt < 4; mt++)
#pragma unroll
        for (int nt = 0; nt < 4; nt++)
#pragma unroll
            for (int r = 0; r < 4; r++) acc[mt][nt][r] = 0.f;

    load_tile(0, 0);
    CP_COMMIT();
    load_tile(1, 1);
    CP_COMMIT();

    int rsel = (lane & 7) + ((lane >> 3) & 1) * 8;
    int csel = (lane >> 4) * 8;

    int stage = 0;
    for (int kt = 0; kt < KT; kt++) {
        CP_WAIT(1);
        __syncthreads();

        uint32_t As_u = smem_b + (uint32_t)stage * STAGE_BYTES;
        uint32_t Bs_u = As_u + TILE_H * 2;

#pragma unroll
        for (int ks = 0; ks < 2; ks++) {
            int col = ks * 16 + csel;
            uint32_t afr[4][4], bfr[4][2];
#pragma unroll
            for (int mt = 0; mt < 4; mt++) {
                uint32_t addr = As_u +
                    (uint32_t)((warp_m * 64 + mt * 16 + rsel) * SROW_H + col) * 2;
                ldsm_x4(afr[mt][0], afr[mt][1], afr[mt][2], afr[mt][3], addr);
            }
#pragma unroll
            for (int p = 0; p < 2; p++) {
                uint32_t addr = Bs_u +
                    (uint32_t)((warp_n * 32 + p * 16 + rsel) * SROW_H + col) * 2;
                uint32_t b0, b1, b2, b3;
                ldsm_x4(b0, b1, b2, b3, addr);
                bfr[p*2  ][0] = b0; bfr[p*2+1][0] = b1;
                bfr[p*2  ][1] = b2; bfr[p*2+1][1] = b3;
            }
#pragma unroll
            for (int mt = 0; mt < 4; mt++)
#pragma unroll
                for (int nt = 0; nt < 4; nt++)
                    mma_f16(acc[mt][nt], afr[mt], bfr[nt]);
        }

        if (kt + 2 < KT) {
            int nstage = stage + 2; if (nstage >= NSTAGE) nstage -= NSTAGE;
            load_tile(kt + 2, nstage);
        }
        CP_COMMIT();
        stage = (stage + 1 == NSTAGE) ? 0 : stage + 1;
    }

    // Epilogue
#pragma unroll
    for (int mt = 0; mt < 4; mt++) {
        int r0 = m0 + warp_m * 64 + mt * 16 + grp;
        int r1 = r0 + 8;
        float bs0 = (MODE == 1) ? bias[r0] : 0.f;
        float bs1 = (MODE == 1) ? bias[r1] : 0.f;
#pragma unroll
        for (int nt = 0; nt < 4; nt++) {
            int n = n0 + warp_n * 32 + nt * 8 + qid * 2;
            float* a4 = acc[mt][nt];
            if (MODE == 0) {
                __half* Ch = (__half*)Cv;
                *(__half2*)(Ch + (size_t)r0 * BP + n) = __floats2half2_rn(a4[0], a4[1]);
                *(__half2*)(Ch + (size_t)r1 * BP + n) = __floats2half2_rn(a4[2], a4[3]);
            } else {
                float* C = (float*)Cv;
                int bb = n / NPIX, p = n - bb * NPIX;
                *(float2*)(C + ((size_t)bb * CIN + r0) * NPIX + p) =
                    make_float2(a4[0] + bs0, a4[1] + bs0);
                *(float2*)(C + ((size_t)bb * CIN + r1) * NPIX + p) =
                    make_float2(a4[2] + bs1, a4[3] + bs1);
            }
        }
    }
}

// ---------------------------------------------------------------------------
// 3) diag: each thread computes 2 adjacent pixels via half2 loads
// ---------------------------------------------------------------------------
__global__ void diag_kernel()
{
    int idx = blockIdx.x * blockDim.x + threadIdx.x;   // over NBH * NPIX/2
    int n2  = idx % (NPIX / 2);
    int bh  = idx / (NPIX / 2);
    int b = bh >> 3, h = bh & 7;
    int n = n2 * 2;
    size_t base = (size_t)b * NPIX + n;
    float s0 = 0.f, s1 = 0.f;
#pragma unroll 8
    for (int d = 0; d < DH; d++) {
        float2 qf = __half22float2(*(const __half2*)(g_q_h  + (size_t)(h * DH + d) * BP + base));
        float2 kf = __half22float2(*(const __half2*)(g_kv_h + (size_t)(h * DH + d) * BP + base));
        s0 += qf.x * kf.x;
        s1 += qf.y * kf.y;
    }
    g_diag[bh * NPIX + n]     = s0 * SCALE_F;
    g_diag[bh * NPIX + n + 1] = s1 * SCALE_F;
}

__global__ void reduce_diag1()
{
    __shared__ float sm[256];
    float s = 0.f;
    for (int i = blockIdx.x * 256 + threadIdx.x; i < NBH * NPIX; i += 256 * 256)
        s += g_diag[i];
    sm[threadIdx.x] = s;
    __syncthreads();
    for (int st = 128; st > 0; st >>= 1) {
        if (threadIdx.x < st) sm[threadIdx.x] += sm[threadIdx.x + st];
        __syncthreads();
    }
    if (threadIdx.x == 0) g_red[blockIdx.x] = sm[0];
}
__global__ void reduce_diag2()
{
    __shared__ float sm[256];
    sm[threadIdx.x] = g_red[threadIdx.x];
    __syncthreads();
    for (int st = 128; st > 0; st >>= 1) {
        if (threadIdx.x < st) sm[threadIdx.x] += sm[threadIdx.x + st];
        __syncthreads();
    }
    if (threadIdx.x == 0) g_m0[0] = sm[0];
}

// ---------------------------------------------------------------------------
// 4) ktv partials (grid NSPLIT x 64) + reduce; half2 global loads, fp32 accum
// ---------------------------------------------------------------------------
__global__ void ktv_partial()
{
    __shared__ float Ks[32][65];
    __shared__ float Vs[32][65];
    int split = blockIdx.x;
    int bh = blockIdx.y;
    int b = bh >> 3, h = bh & 7;
    int tid = threadIdx.x;
    int ty = tid >> 4, tx = tid & 15;

    float acc[4][4];
#pragma unroll
    for (int i = 0; i < 4; i++)
#pragma unroll
        for (int j = 0; j < 4; j++) acc[i][j] = 0.f;

    size_t base = (size_t)b * NPIX;
    int n_start = split * (NPIX / NSPLIT);

    for (int n0 = n_start; n0 < n_start + (NPIX / NSPLIT); n0 += 32) {
#pragma unroll
        for (int l = 0; l < 4; l++) {
            int e  = tid + l * 256;       // 0..1023
            int d  = e >> 4;              // 0..63
            int nn = (e & 15) * 2;        // 0,2,..30
            float2 kf = __half22float2(*(const __half2*)(g_kv_h + (size_t)(h * DH + d) * BP + base + n0 + nn));
            float2 vf = __half22float2(*(const __half2*)(g_kv_h + (size_t)(INNER + h * DH + d) * BP + base + n0 + nn));
            Ks[nn][d] = kf.x;  Ks[nn + 1][d] = kf.y;
            Vs[nn][d] = vf.x;  Vs[nn + 1][d] = vf.y;
        }
        __syncthreads();
#pragma unroll
        for (int nn = 0; nn < 32; nn++) {
            float a[4], bb[4];
#pragma unroll
            for (int i = 0; i < 4; i++) a[i]  = Ks[nn][ty * 4 + i];
#pragma unroll
            for (int j = 0; j < 4; j++) bb[j] = Vs[nn][tx * 4 + j];
#pragma unroll
            for (int i = 0; i < 4; i++)
#pragma unroll
                for (int j = 0; j < 4; j++) acc[i][j] += a[i] * bb[j];
        }
        __syncthreads();
    }
    float* dst = g_ktvp + ((size_t)(split * NBH + bh)) * (DH * DH);
#pragma unroll
    for (int i = 0; i < 4; i++)
#pragma unroll
        for (int j = 0; j < 4; j++)
            dst[(ty * 4 + i) * DH + tx * 4 + j] = acc[i][j];
}

__global__ void ktv_reduce()
{
    int idx = blockIdx.x * blockDim.x + threadIdx.x;
    if (idx >= NBH * DH * DH) return;
    float s = 0.f;
#pragma unroll
    for (int sp = 0; sp < NSPLIT; sp++)
        s += g_ktvp[(size_t)sp * (NBH * DH * DH) + idx];
    g_ktv[idx] = s;
}

// ---------------------------------------------------------------------------
// 5) att_out: 64 pixels per block, each thread handles 2 pixels x 8 e values.
// ---------------------------------------------------------------------------
__global__ void att_out_kernel()
{
    __shared__ float ktv_s[DH * DH];
    int bh = blockIdx.y;
    int b = bh >> 3, h = bh & 7;

    for (int i = threadIdx.x; i < DH * DH; i += 256)
        ktv_s[i] = g_ktv[bh * (DH * DH) + i];
    __syncthreads();

    float m0 = g_m0[0];
    int pn = threadIdx.x & 31;               // pixel pair 0..31
    int eg = threadIdx.x >> 5;                // 0..7
    int n = blockIdx.x * 64 + pn * 2;
    size_t base = (size_t)b * NPIX + n;

    float acc0[8], acc1[8];
#pragma unroll
    for (int j = 0; j < 8; j++) { acc0[j] = 0.f; acc1[j] = 0.f; }

#pragma unroll 4
    for (int d = 0; d < DH; d++) {
        float2 qf = __half22float2(*(const __half2*)(g_q_h + (size_t)(h * DH + d) * BP + base));
        const float* kv = ktv_s + d * DH + eg * 8;
#pragma unroll
        for (int j = 0; j < 8; j++) {
            acc0[j] += qf.x * kv[j];
            acc1[j] += qf.y * kv[j];
        }
    }

    float c0 = m0 - g_diag[bh * NPIX + n];
    float c1 = m0 - g_diag[bh * NPIX + n + 1];
    __half out0[8], out1[8];
#pragma unroll
    for (int j = 0; j < 8; j++) {
        int e = eg * 8 + j;
        float2 vf = __half22float2(*(const __half2*)(g_kv_h + (size_t)(INNER + h * DH + e) * BP + base));
        out0[j] = __float2half_rn(SCALE_F * acc0[j] + c0 * vf.x);
        out1[j] = __float2half_rn(SCALE_F * acc1[j] + c1 * vf.y);
    }
    __half2* d0 = (__half2*)(g_att_h + base * INNER + h * DH + eg * 8);
    __half2* d1 = (__half2*)(g_att_h + (base + 1) * INNER + h * DH + eg * 8);
#pragma unroll
    for (int j = 0; j < 4; j++) {
        d0[j] = __halves2half2(out0[j*2], out0[j*2+1]);
        d1[j] = __halves2half2(out1[j*2], out1[j*2+1]);
    }
}

// ---------------------------------------------------------------------------
// Launch
// ---------------------------------------------------------------------------
extern "C" void kernel_launch(void* const* d_in, const int* in_sizes, int n_in,
                              void* d_out, int out_size)
{
    const float* x       = (const float*)d_in[0];
    const float* wq_dw   = (const float*)d_in[1];
    const float* wq_g    = (const float*)d_in[2];
    const float* wq_b    = (const float*)d_in[3];
    const float* wq_m    = (const float*)d_in[4];
    const float* wq_v    = (const float*)d_in[5];
    const float* wq_pw   = (const float*)d_in[6];
    const float* wkv_dw  = (const float*)d_in[7];
    const float* wkv_g   = (const float*)d_in[8];
    const float* wkv_b   = (const float*)d_in[9];
    const float* wkv_m   = (const float*)d_in[10];
    const float* wkv_v   = (const float*)d_in[11];
    const float* wkv_pw  = (const float*)d_in[12];
    const float* wo      = (const float*)d_in[13];
    const float* bo      = (const float*)d_in[14];
    float* out = (float*)d_out;

    __half *p_yq, *p_ykv, *p_att, *p_wq, *p_wkv, *p_wo, *p_q, *p_kv;
    cudaGetSymbolAddress((void**)&p_yq,  g_yq_h);
    cudaGetSymbolAddress((void**)&p_ykv, g_ykv_h);
    cudaGetSymbolAddress((void**)&p_q,   g_q_h);
    cudaGetSymbolAddress((void**)&p_kv,  g_kv_h);
    cudaGetSymbolAddress((void**)&p_att, g_att_h);
    cudaGetSymbolAddress((void**)&p_wq,  g_wq_h);
    cudaGetSymbolAddress((void**)&p_wkv, g_wkv_h);
    cudaGetSymbolAddress((void**)&p_wo,  g_wo_h);

    cudaFuncSetAttribute(gemm_f16<0>, cudaFuncAttributeMaxDynamicSharedMemorySize, SMEM_GEMM_BYTES);
    cudaFuncSetAttribute(gemm_f16<1>, cudaFuncAttributeMaxDynamicSharedMemorySize, SMEM_GEMM_BYTES);

    // 0) weight conversion to fp16
    cvt_weights_kernel<<<(NW1 + NW2 + NW3 + 255) / 256, 256>>>(wq_pw, wkv_pw, wo);

    // 1) depthwise conv + BN (halo-tiled, [n][c] fp16 output)
    dwconv_bn_kernel<<<dim3(7, 48, 8), 256>>>(
        x, wq_dw, wq_g, wq_b, wq_m, wq_v,
           wkv_dw, wkv_g, wkv_b, wkv_m, wkv_v);

    // 2) pointwise projections on tensor cores (fp16 out)
    gemm_f16<0><<<dim3(196, 4), 256, SMEM_GEMM_BYTES>>>(p_wq,  p_yq,  p_q,  CIN, nullptr);
    gemm_f16<0><<<dim3(196, 8), 256, SMEM_GEMM_BYTES>>>(p_wkv, p_ykv, p_kv, CIN, nullptr);

    // 3) attention middle (half2 loads, fp32 accumulate)
    diag_kernel<<<(NBH * NPIX / 2) / 256, 256>>>();
    reduce_diag1<<<256, 256>>>();
    reduce_diag2<<<1, 256>>>();
    ktv_partial<<<dim3(NSPLIT, NBH), 256>>>();
    ktv_reduce<<<(NBH * DH * DH) / 256, 256>>>();
    att_out_kernel<<<dim3(NPIX / 64, NBH), 256>>>();

    // 4) output projection (+bias, NCHW scatter)
    gemm_f16<1><<<dim3(196, 3), 256, SMEM_GEMM_BYTES>>>(p_wo, p_att, out, INNER, bo);
}

// round 12
// speedup vs baseline: 1.2881x; 1.2881x over previous
#include <cuda_runtime.h>
#include <cuda_fp16.h>
#include <cstdint>

// Problem constants
#define BATCH   8
#define CIN     384
#define NPIX    3136           // 56*56
#define WWID    56
#define BP      25088          // BATCH*NPIX
#define INNER   512
#define KVOUT   1024
#define HEADS   8
#define DH      64
#define NBH     64
#define SCALE_F 0.125f
#define EPS_F   1e-5f
#define NSPLIT  7

// ---------------------------------------------------------------------------
// Scratch (device globals)
// ---------------------------------------------------------------------------
__device__ __align__(16) __half g_yq_h [(size_t)BP * CIN];   // dwconv out, q path  [n][c]
__device__ __align__(16) __half g_ykv_h[(size_t)BP * CIN];   // dwconv out, kv path [n][c]
__device__ __align__(16) __half g_q_h [(size_t)INNER * BP];  // q   [m][n] fp16
__device__ __align__(16) __half g_kv_h[(size_t)KVOUT * BP];  // k|v [m][n] fp16
__device__ __align__(16) __half g_att_h[(size_t)BP * INNER]; // attention out [n][o]
__device__ __align__(16) __half g_wq_h [INNER * CIN];        // fp16 weights
__device__ __align__(16) __half g_wkv_h[KVOUT * CIN];
__device__ __align__(16) __half g_wo_h [CIN * INNER];
__device__ float g_diag[NBH * NPIX];
__device__ float g_ktvp[NSPLIT * NBH * DH * DH];
__device__ float g_ktv [NBH * DH * DH];
__device__ float g_red[256];
__device__ float g_m0[1];

// ---------------------------------------------------------------------------
// Helpers
// ---------------------------------------------------------------------------
__device__ __forceinline__ uint32_t smem_u32(const void* p) {
    uint32_t a;
    asm("{ .reg .u64 t; cvta.to.shared.u64 t, %1; cvt.u32.u64 %0, t; }" : "=r"(a) : "l"(p));
    return a;
}
__device__ __forceinline__ void cp_async16(uint32_t dst, const void* src) {
    asm volatile("cp.async.cg.shared.global [%0], [%1], 16;" :: "r"(dst), "l"(src));
}
#define CP_COMMIT() asm volatile("cp.async.commit_group;" ::: "memory")
#define CP_WAIT(N)  asm volatile("cp.async.wait_group %0;" :: "n"(N) : "memory")

__device__ __forceinline__ void mma_f16(float* c, const uint32_t* a, const uint32_t* b) {
    asm volatile(
        "mma.sync.aligned.m16n8k16.row.col.f32.f16.f16.f32 "
        "{%0,%1,%2,%3}, {%4,%5,%6,%7}, {%8,%9}, {%0,%1,%2,%3};"
        : "+f"(c[0]), "+f"(c[1]), "+f"(c[2]), "+f"(c[3])
        : "r"(a[0]), "r"(a[1]), "r"(a[2]), "r"(a[3]), "r"(b[0]), "r"(b[1]));
}
__device__ __forceinline__ void ldsm_x4(uint32_t& r0, uint32_t& r1, uint32_t& r2, uint32_t& r3,
                                        uint32_t addr) {
    asm volatile("ldmatrix.sync.aligned.m8n8.x4.shared.b16 {%0,%1,%2,%3}, [%4];"
                 : "=r"(r0), "=r"(r1), "=r"(r2), "=r"(r3) : "r"(addr));
}

// ---------------------------------------------------------------------------
// 0) Weight conversion (fp32 -> fp16), all three weights in one launch
// ---------------------------------------------------------------------------
#define NW1 (INNER * CIN)
#define NW2 (KVOUT * CIN)
#define NW3 (CIN * INNER)
__global__ void cvt_weights_kernel(const float* __restrict__ s1, const float* __restrict__ s2,
                                   const float* __restrict__ s3)
{
    int i = blockIdx.x * 256 + threadIdx.x;
    if (i < NW1) {
        g_wq_h[i] = __float2half_rn(s1[i]);
    } else if (i < NW1 + NW2) {
        g_wkv_h[i - NW1] = __float2half_rn(s2[i - NW1]);
    } else if (i < NW1 + NW2 + NW3) {
        g_wo_h[i - NW1 - NW2] = __float2half_rn(s3[i - NW1 - NW2]);
    }
}

// ---------------------------------------------------------------------------
// 1) Depthwise 3x3 conv + BN (round-10 structure), output TRANSPOSED [n][c] fp16
// ---------------------------------------------------------------------------
__global__ void dwconv_bn_kernel(
    const float* __restrict__ x,
    const float* __restrict__ w1, const float* __restrict__ g1, const float* __restrict__ b1,
    const float* __restrict__ m1, const float* __restrict__ v1,
    const float* __restrict__ w2, const float* __restrict__ g2, const float* __restrict__ b2,
    const float* __restrict__ m2, const float* __restrict__ v2)
{
    __shared__ float s1[32][65];
    __shared__ float s2[32][65];
    int b  = blockIdx.z;
    int ct = blockIdx.y;     // 12 channel tiles of 32
    int pt = blockIdx.x;     // 49 pixel tiles of 64
    int tid = threadIdx.x;
    int p_loc = tid & 63;
    int c_sub = tid >> 6;
    int p = pt * 64 + p_loc;
    int h = p / WWID, w = p % WWID;

#pragma unroll
    for (int i = 0; i < 8; i++) {
        int c_loc = i * 4 + c_sub;
        int c = ct * 32 + c_loc;
        const float* xb = x + ((size_t)(b * CIN + c)) * NPIX;
        float acc1 = 0.f, acc2 = 0.f;
#pragma unroll
        for (int kh = 0; kh < 3; kh++) {
            int hh = h + kh - 1;
            if (hh < 0 || hh >= WWID) continue;
#pragma unroll
            for (int kw = 0; kw < 3; kw++) {
                int ww2 = w + kw - 1;
                if (ww2 < 0 || ww2 >= WWID) continue;
                float xv = xb[hh * WWID + ww2];
                acc1 += xv * w1[c * 9 + kh * 3 + kw];
                acc2 += xv * w2[c * 9 + kh * 3 + kw];
            }
        }
        float inv1 = g1[c] * rsqrtf(v1[c] + EPS_F);
        float inv2 = g2[c] * rsqrtf(v2[c] + EPS_F);
        s1[c_loc][p_loc] = acc1 * inv1 + (b1[c] - m1[c] * inv1);
        s2[c_loc][p_loc] = acc2 * inv2 + (b2[c] - m2[c] * inv2);
    }
    __syncthreads();

#pragma unroll
    for (int i = 0; i < 2; i++) {
        int idx = tid + i * 256;
        int pp  = idx >> 3;
        int cq  = idx & 7;
        size_t base = ((size_t)(b * NPIX + pt * 64 + pp)) * CIN + ct * 32 + cq * 4;
        __half2 q0 = __floats2half2_rn(s1[cq*4+0][pp], s1[cq*4+1][pp]);
        __half2 q1 = __floats2half2_rn(s1[cq*4+2][pp], s1[cq*4+3][pp]);
        __half2 k0 = __floats2half2_rn(s2[cq*4+0][pp], s2[cq*4+1][pp]);
        __half2 k1 = __floats2half2_rn(s2[cq*4+2][pp], s2[cq*4+3][pp]);
        *(__half2*)(g_yq_h  + base)     = q0;
        *(__half2*)(g_yq_h  + base + 2) = q1;
        *(__half2*)(g_ykv_h + base)     = k0;
        *(__half2*)(g_ykv_h + base + 2) = k1;
    }
}

// ---------------------------------------------------------------------------
// 2) fp16 mma.sync GEMM, 4-stage cp.async pipeline, ldmatrix fragments.
//    C[m][n] = sum_k A[m][k] * B[n][k], fp32 accum.
//    MODE 0: fp16 output to C[m*BP + n].  MODE 1: fp32 NCHW scatter + bias.
// ---------------------------------------------------------------------------
#define KTILE   32                        // halves per k-tile
#define SROW_H  40                        // halves per SMEM row (80B stride)
#define TILE_H  (128 * SROW_H)            // halves per operand tile
#define NSTAGE  4
#define STAGE_BYTES (2 * TILE_H * 2)      // A+B per stage
#define SMEM_GEMM_BYTES (NSTAGE * STAGE_BYTES)

template<int MODE>
__global__ void __launch_bounds__(256, 2) gemm_f16(
    const __half* __restrict__ A, const __half* __restrict__ Bm,
    void* __restrict__ Cv, int Kd, const float* __restrict__ bias)
{
    extern __shared__ __half smem[];
    int tid = threadIdx.x;
    int wid = tid >> 5;
    int lane = tid & 31;
    int grp = lane >> 2;          // 0..7
    int qid = lane & 3;           // 0..3
    int warp_m = wid & 1;
    int warp_n = wid >> 1;

    int n0 = blockIdx.x * 128;
    int m0 = blockIdx.y * 128;
    int KT = Kd / KTILE;          // 12 or 16 (>= 3)

    uint32_t smem_b = smem_u32(smem);

    auto load_tile = [&](int kt, int stage) {
        int k0 = kt * KTILE;
        uint32_t dA = smem_b + (uint32_t)stage * STAGE_BYTES;
        uint32_t dB = dA + TILE_H * 2;
#pragma unroll
        for (int i = 0; i < 2; i++) {
            int idx = tid + i * 256;
            int row = idx >> 2, q = idx & 3;
            cp_async16(dA + (uint32_t)(row * SROW_H + q * 8) * 2,
                       A + (size_t)(m0 + row) * Kd + k0 + q * 8);
        }
#pragma unroll
        for (int i = 0; i < 2; i++) {
            int idx = tid + i * 256;
            int row = idx >> 2, q = idx & 3;
            cp_async16(dB + (uint32_t)(row * SROW_H + q * 8) * 2,
                       Bm + (size_t)(n0 + row) * Kd + k0 + q * 8);
        }
    };

    float acc[4][4][4];
#pragma unroll
    for (int mt = 0; mt < 4; mt++)
#pragma unroll
        for (int nt = 0; nt < 4; nt++)
#pragma unroll
            for (int r = 0; r < 4; r++) acc[mt][nt][r] = 0.f;

    // Prologue: 3 tiles in flight
    load_tile(0, 0);
    CP_COMMIT();
    load_tile(1, 1);
    CP_COMMIT();
    load_tile(2, 2);
    CP_COMMIT();

    int rsel = (lane & 7) + ((lane >> 3) & 1) * 8;
    int csel = (lane >> 4) * 8;

    int stage = 0;
    for (int kt = 0; kt < KT; kt++) {
        CP_WAIT(2);               // tile kt resident (2 younger groups may be pending)
        __syncthreads();          // all warps past compute of tile kt-1

        uint32_t As_u = smem_b + (uint32_t)stage * STAGE_BYTES;
        uint32_t Bs_u = As_u + TILE_H * 2;

#pragma unroll
        for (int ks = 0; ks < 2; ks++) {
            int col = ks * 16 + csel;
            uint32_t afr[4][4], bfr[4][2];
#pragma unroll
            for (int mt = 0; mt < 4; mt++) {
                uint32_t addr = As_u +
                    (uint32_t)((warp_m * 64 + mt * 16 + rsel) * SROW_H + col) * 2;
                ldsm_x4(afr[mt][0], afr[mt][1], afr[mt][2], afr[mt][3], addr);
            }
#pragma unroll
            for (int p = 0; p < 2; p++) {
                uint32_t addr = Bs_u +
                    (uint32_t)((warp_n * 32 + p * 16 + rsel) * SROW_H + col) * 2;
                uint32_t b0, b1, b2, b3;
                ldsm_x4(b0, b1, b2, b3, addr);
                bfr[p*2  ][0] = b0; bfr[p*2+1][0] = b1;
                bfr[p*2  ][1] = b2; bfr[p*2+1][1] = b3;
            }
#pragma unroll
            for (int mt = 0; mt < 4; mt++)
#pragma unroll
                for (int nt = 0; nt < 4; nt++)
                    mma_f16(acc[mt][nt], afr[mt], bfr[nt]);
        }

        // issue loads for tile kt+3 into stage (stage+3)%4 (holds tile kt-1, done)
        if (kt + 3 < KT) {
            int nstage = stage + 3; if (nstage >= NSTAGE) nstage -= NSTAGE;
            load_tile(kt + 3, nstage);
        }
        CP_COMMIT();              // keep group count aligned even when empty
        stage = (stage + 1 == NSTAGE) ? 0 : stage + 1;
    }

    // Epilogue
#pragma unroll
    for (int mt = 0; mt < 4; mt++) {
        int r0 = m0 + warp_m * 64 + mt * 16 + grp;
        int r1 = r0 + 8;
        float bs0 = (MODE == 1) ? bias[r0] : 0.f;
        float bs1 = (MODE == 1) ? bias[r1] : 0.f;
#pragma unroll
        for (int nt = 0; nt < 4; nt++) {
            int n = n0 + warp_n * 32 + nt * 8 + qid * 2;
            float* a4 = acc[mt][nt];
            if (MODE == 0) {
                __half* Ch = (__half*)Cv;
                *(__half2*)(Ch + (size_t)r0 * BP + n) = __floats2half2_rn(a4[0], a4[1]);
                *(__half2*)(Ch + (size_t)r1 * BP + n) = __floats2half2_rn(a4[2], a4[3]);
            } else {
                float* C = (float*)Cv;
                int bb = n / NPIX, p = n - bb * NPIX;
                *(float2*)(C + ((size_t)bb * CIN + r0) * NPIX + p) =
                    make_float2(a4[0] + bs0, a4[1] + bs0);
                *(float2*)(C + ((size_t)bb * CIN + r1) * NPIX + p) =
                    make_float2(a4[2] + bs1, a4[3] + bs1);
            }
        }
    }
}

// ---------------------------------------------------------------------------
// 3) diag: each thread computes 2 adjacent pixels via half2 loads
// ---------------------------------------------------------------------------
__global__ void diag_kernel()
{
    int idx = blockIdx.x * blockDim.x + threadIdx.x;   // over NBH * NPIX/2
    int n2  = idx % (NPIX / 2);
    int bh  = idx / (NPIX / 2);
    int b = bh >> 3, h = bh & 7;
    int n = n2 * 2;
    size_t base = (size_t)b * NPIX + n;
    float s0 = 0.f, s1 = 0.f;
#pragma unroll 8
    for (int d = 0; d < DH; d++) {
        float2 qf = __half22float2(*(const __half2*)(g_q_h  + (size_t)(h * DH + d) * BP + base));
        float2 kf = __half22float2(*(const __half2*)(g_kv_h + (size_t)(h * DH + d) * BP + base));
        s0 += qf.x * kf.x;
        s1 += qf.y * kf.y;
    }
    g_diag[bh * NPIX + n]     = s0 * SCALE_F;
    g_diag[bh * NPIX + n + 1] = s1 * SCALE_F;
}

__global__ void reduce_diag1()
{
    __shared__ float sm[256];
    float s = 0.f;
    for (int i = blockIdx.x * 256 + threadIdx.x; i < NBH * NPIX; i += 256 * 256)
        s += g_diag[i];
    sm[threadIdx.x] = s;
    __syncthreads();
    for (int st = 128; st > 0; st >>= 1) {
        if (threadIdx.x < st) sm[threadIdx.x] += sm[threadIdx.x + st];
        __syncthreads();
    }
    if (threadIdx.x == 0) g_red[blockIdx.x] = sm[0];
}
__global__ void reduce_diag2()
{
    __shared__ float sm[256];
    sm[threadIdx.x] = g_red[threadIdx.x];
    __syncthreads();
    for (int st = 128; st > 0; st >>= 1) {
        if (threadIdx.x < st) sm[threadIdx.x] += sm[threadIdx.x + st];
        __syncthreads();
    }
    if (threadIdx.x == 0) g_m0[0] = sm[0];
}

// ---------------------------------------------------------------------------
// 4) ktv partials (grid NSPLIT x 64) + reduce; half2 global loads, fp32 accum
// ---------------------------------------------------------------------------
__global__ void ktv_partial()
{
    __shared__ float Ks[32][65];
    __shared__ float Vs[32][65];
    int split = blockIdx.x;
    int bh = blockIdx.y;
    int b = bh >> 3, h = bh & 7;
    int tid = threadIdx.x;
    int ty = tid >> 4, tx = tid & 15;

    float acc[4][4];
#pragma unroll
    for (int i = 0; i < 4; i++)
#pragma unroll
        for (int j = 0; j < 4; j++) acc[i][j] = 0.f;

    size_t base = (size_t)b * NPIX;
    int n_start = split * (NPIX / NSPLIT);

    for (int n0 = n_start; n0 < n_start + (NPIX / NSPLIT); n0 += 32) {
#pragma unroll
        for (int l = 0; l < 4; l++) {
            int e  = tid + l * 256;       // 0..1023
            int d  = e >> 4;              // 0..63
            int nn = (e & 15) * 2;        // 0,2,..30
            float2 kf = __half22float2(*(const __half2*)(g_kv_h + (size_t)(h * DH + d) * BP + base + n0 + nn));
            float2 vf = __half22float2(*(const __half2*)(g_kv_h + (size_t)(INNER + h * DH + d) * BP + base + n0 + nn));
            Ks[nn][d] = kf.x;  Ks[nn + 1][d] = kf.y;
            Vs[nn][d] = vf.x;  Vs[nn + 1][d] = vf.y;
        }
        __syncthreads();
#pragma unroll
        for (int nn = 0; nn < 32; nn++) {
            float a[4], bb[4];
#pragma unroll
            for (int i = 0; i < 4; i++) a[i]  = Ks[nn][ty * 4 + i];
#pragma unroll
            for (int j = 0; j < 4; j++) bb[j] = Vs[nn][tx * 4 + j];
#pragma unroll
            for (int i = 0; i < 4; i++)
#pragma unroll
                for (int j = 0; j < 4; j++) acc[i][j] += a[i] * bb[j];
        }
        __syncthreads();
    }
    float* dst = g_ktvp + ((size_t)(split * NBH + bh)) * (DH * DH);
#pragma unroll
    for (int i = 0; i < 4; i++)
#pragma unroll
        for (int j = 0; j < 4; j++)
            dst[(ty * 4 + i) * DH + tx * 4 + j] = acc[i][j];
}

__global__ void ktv_reduce()
{
    int idx = blockIdx.x * blockDim.x + threadIdx.x;
    if (idx >= NBH * DH * DH) return;
    float s = 0.f;
#pragma unroll
    for (int sp = 0; sp < NSPLIT; sp++)
        s += g_ktvp[(size_t)sp * (NBH * DH * DH) + idx];
    g_ktv[idx] = s;
}

// ---------------------------------------------------------------------------
// 5) att_out: 64 pixels per block, each thread handles 2 pixels x 8 e values.
// ---------------------------------------------------------------------------
__global__ void att_out_kernel()
{
    __shared__ float ktv_s[DH * DH];
    int bh = blockIdx.y;
    int b = bh >> 3, h = bh & 7;

    for (int i = threadIdx.x; i < DH * DH; i += 256)
        ktv_s[i] = g_ktv[bh * (DH * DH) + i];
    __syncthreads();

    float m0 = g_m0[0];
    int pn = threadIdx.x & 31;               // pixel pair 0..31
    int eg = threadIdx.x >> 5;                // 0..7
    int n = blockIdx.x * 64 + pn * 2;
    size_t base = (size_t)b * NPIX + n;

    float acc0[8], acc1[8];
#pragma unroll
    for (int j = 0; j < 8; j++) { acc0[j] = 0.f; acc1[j] = 0.f; }

#pragma unroll 4
    for (int d = 0; d < DH; d++) {
        float2 qf = __half22float2(*(const __half2*)(g_q_h + (size_t)(h * DH + d) * BP + base));
        const float* kv = ktv_s + d * DH + eg * 8;
#pragma unroll
        for (int j = 0; j < 8; j++) {
            acc0[j] += qf.x * kv[j];
            acc1[j] += qf.y * kv[j];
        }
    }

    float c0 = m0 - g_diag[bh * NPIX + n];
    float c1 = m0 - g_diag[bh * NPIX + n + 1];
    __half out0[8], out1[8];
#pragma unroll
    for (int j = 0; j < 8; j++) {
        int e = eg * 8 + j;
        float2 vf = __half22float2(*(const __half2*)(g_kv_h + (size_t)(INNER + h * DH + e) * BP + base));
        out0[j] = __float2half_rn(SCALE_F * acc0[j] + c0 * vf.x);
        out1[j] = __float2half_rn(SCALE_F * acc1[j] + c1 * vf.y);
    }
    __half2* d0 = (__half2*)(g_att_h + base * INNER + h * DH + eg * 8);
    __half2* d1 = (__half2*)(g_att_h + (base + 1) * INNER + h * DH + eg * 8);
#pragma unroll
    for (int j = 0; j < 4; j++) {
        d0[j] = __halves2half2(out0[j*2], out0[j*2+1]);
        d1[j] = __halves2half2(out1[j*2], out1[j*2+1]);
    }
}

// ---------------------------------------------------------------------------
// Launch
// ---------------------------------------------------------------------------
extern "C" void kernel_launch(void* const* d_in, const int* in_sizes, int n_in,
                              void* d_out, int out_size)
{
    const float* x       = (const float*)d_in[0];
    const float* wq_dw   = (const float*)d_in[1];
    const float* wq_g    = (const float*)d_in[2];
    const float* wq_b    = (const float*)d_in[3];
    const float* wq_m    = (const float*)d_in[4];
    const float* wq_v    = (const float*)d_in[5];
    const float* wq_pw   = (const float*)d_in[6];
    const float* wkv_dw  = (const float*)d_in[7];
    const float* wkv_g   = (const float*)d_in[8];
    const float* wkv_b   = (const float*)d_in[9];
    const float* wkv_m   = (const float*)d_in[10];
    const float* wkv_v   = (const float*)d_in[11];
    const float* wkv_pw  = (const float*)d_in[12];
    const float* wo      = (const float*)d_in[13];
    const float* bo      = (const float*)d_in[14];
    float* out = (float*)d_out;

    __half *p_yq, *p_ykv, *p_att, *p_wq, *p_wkv, *p_wo, *p_q, *p_kv;
    cudaGetSymbolAddress((void**)&p_yq,  g_yq_h);
    cudaGetSymbolAddress((void**)&p_ykv, g_ykv_h);
    cudaGetSymbolAddress((void**)&p_q,   g_q_h);
    cudaGetSymbolAddress((void**)&p_kv,  g_kv_h);
    cudaGetSymbolAddress((void**)&p_att, g_att_h);
    cudaGetSymbolAddress((void**)&p_wq,  g_wq_h);
    cudaGetSymbolAddress((void**)&p_wkv, g_wkv_h);
    cudaGetSymbolAddress((void**)&p_wo,  g_wo_h);

    cudaFuncSetAttribute(gemm_f16<0>, cudaFuncAttributeMaxDynamicSharedMemorySize, SMEM_GEMM_BYTES);
    cudaFuncSetAttribute(gemm_f16<1>, cudaFuncAttributeMaxDynamicSharedMemorySize, SMEM_GEMM_BYTES);

    // 0) weight conversion to fp16
    cvt_weights_kernel<<<(NW1 + NW2 + NW3 + 255) / 256, 256>>>(wq_pw, wkv_pw, wo);

    // 1) depthwise conv + BN (transposed [n][c] fp16 output)
    dwconv_bn_kernel<<<dim3(49, 12, 8), 256>>>(
        x, wq_dw, wq_g, wq_b, wq_m, wq_v,
           wkv_dw, wkv_g, wkv_b, wkv_m, wkv_v);

    // 2) pointwise projections on tensor cores (4-stage pipeline)
    gemm_f16<0><<<dim3(196, 4), 256, SMEM_GEMM_BYTES>>>(p_wq,  p_yq,  p_q,  CIN, nullptr);
    gemm_f16<0><<<dim3(196, 8), 256, SMEM_GEMM_BYTES>>>(p_wkv, p_ykv, p_kv, CIN, nullptr);

    // 3) attention middle (half2 loads, fp32 accumulate)
    diag_kernel<<<(NBH * NPIX / 2) / 256, 256>>>();
    reduce_diag1<<<256, 256>>>();
    reduce_diag2<<<1, 256>>>();
    ktv_partial<<<dim3(NSPLIT, NBH), 256>>>();
    ktv_reduce<<<(NBH * DH * DH) / 256, 256>>>();
    att_out_kernel<<<dim3(NPIX / 64, NBH), 256>>>();

    // 4) output projection (+bias, NCHW scatter)
    gemm_f16<1><<<dim3(196, 3), 256, SMEM_GEMM_BYTES>>>(p_wo, p_att, out, INNER, bo);
}

// round 13
// speedup vs baseline: 1.4131x; 1.0970x over previous
#include <cuda_runtime.h>
#include <cuda_fp16.h>
#include <cstdint>

// Problem constants
#define BATCH   8
#define CIN     384
#define NPIX    3136           // 56*56
#define WWID    56
#define BP      25088          // BATCH*NPIX
#define INNER   512
#define KVOUT   1024
#define HEADS   8
#define DH      64
#define NBH     64
#define SCALE_F 0.125f
#define EPS_F   1e-5f
#define NSPLIT  7

// ---------------------------------------------------------------------------
// Scratch (device globals)
// ---------------------------------------------------------------------------
__device__ __align__(16) __half g_yq_h [(size_t)BP * CIN];   // dwconv out, q path  [n][c]
__device__ __align__(16) __half g_ykv_h[(size_t)BP * CIN];   // dwconv out, kv path [n][c]
__device__ __align__(16) __half g_q_h [(size_t)INNER * BP];  // q   [m][n] fp16
__device__ __align__(16) __half g_kv_h[(size_t)KVOUT * BP];  // k|v [m][n] fp16
__device__ __align__(16) __half g_att_h[(size_t)BP * INNER]; // attention out [n][o]
__device__ __align__(16) __half g_wq_h [INNER * CIN];        // fp16 weights
__device__ __align__(16) __half g_wkv_h[KVOUT * CIN];
__device__ __align__(16) __half g_wo_h [CIN * INNER];
__device__ float g_diag[NBH * NPIX];
__device__ float g_ktvp[NSPLIT * NBH * DH * DH];
__device__ float g_ktv [NBH * DH * DH];
__device__ float g_red[256];
__device__ float g_m0[1];

// ---------------------------------------------------------------------------
// Helpers
// ---------------------------------------------------------------------------
__device__ __forceinline__ uint32_t smem_u32(const void* p) {
    uint32_t a;
    asm("{ .reg .u64 t; cvta.to.shared.u64 t, %1; cvt.u32.u64 %0, t; }" : "=r"(a) : "l"(p));
    return a;
}
__device__ __forceinline__ void cp_async16(uint32_t dst, const void* src) {
    asm volatile("cp.async.cg.shared.global [%0], [%1], 16;" :: "r"(dst), "l"(src));
}
#define CP_COMMIT() asm volatile("cp.async.commit_group;" ::: "memory")
#define CP_WAIT(N)  asm volatile("cp.async.wait_group %0;" :: "n"(N) : "memory")

__device__ __forceinline__ void mma_f16(float* c, const uint32_t* a, const uint32_t* b) {
    asm volatile(
        "mma.sync.aligned.m16n8k16.row.col.f32.f16.f16.f32 "
        "{%0,%1,%2,%3}, {%4,%5,%6,%7}, {%8,%9}, {%0,%1,%2,%3};"
        : "+f"(c[0]), "+f"(c[1]), "+f"(c[2]), "+f"(c[3])
        : "r"(a[0]), "r"(a[1]), "r"(a[2]), "r"(a[3]), "r"(b[0]), "r"(b[1]));
}
__device__ __forceinline__ void ldsm_x4(uint32_t& r0, uint32_t& r1, uint32_t& r2, uint32_t& r3,
                                        uint32_t addr) {
    asm volatile("ldmatrix.sync.aligned.m8n8.x4.shared.b16 {%0,%1,%2,%3}, [%4];"
                 : "=r"(r0), "=r"(r1), "=r"(r2), "=r"(r3) : "r"(addr));
}

// ---------------------------------------------------------------------------
// 0) Weight conversion (fp32 -> fp16), all three weights in one launch
// ---------------------------------------------------------------------------
#define NW1 (INNER * CIN)
#define NW2 (KVOUT * CIN)
#define NW3 (CIN * INNER)
__global__ void cvt_weights_kernel(const float* __restrict__ s1, const float* __restrict__ s2,
                                   const float* __restrict__ s3)
{
    int i = blockIdx.x * 256 + threadIdx.x;
    if (i < NW1) {
        g_wq_h[i] = __float2half_rn(s1[i]);
    } else if (i < NW1 + NW2) {
        g_wkv_h[i - NW1] = __float2half_rn(s2[i - NW1]);
    } else if (i < NW1 + NW2 + NW3) {
        g_wo_h[i - NW1 - NW2] = __float2half_rn(s3[i - NW1 - NW2]);
    }
}

// ---------------------------------------------------------------------------
// 1) Depthwise 3x3 conv + BN, output TRANSPOSED [n][c] fp16.
//    Each thread computes 2 adjacent pixels x 4 channels (shared 3x4 window).
// ---------------------------------------------------------------------------
__global__ void dwconv_bn_kernel(
    const float* __restrict__ x,
    const float* __restrict__ w1, const float* __restrict__ g1, const float* __restrict__ b1,
    const float* __restrict__ m1, const float* __restrict__ v1,
    const float* __restrict__ w2, const float* __restrict__ g2, const float* __restrict__ b2,
    const float* __restrict__ m2, const float* __restrict__ v2)
{
    __shared__ float s1[32][65];
    __shared__ float s2[32][65];
    int b  = blockIdx.z;
    int ct = blockIdx.y;     // 12 channel tiles of 32
    int pt = blockIdx.x;     // 49 pixel tiles of 64
    int tid = threadIdx.x;
    int p2    = tid & 31;    // pixel pair 0..31
    int c_sub = tid >> 5;    // 0..7
    int p = pt * 64 + p2 * 2;
    int h = p / WWID, w = p % WWID;   // p even -> both pixels in same row

#pragma unroll
    for (int i = 0; i < 4; i++) {
        int c_loc = i * 8 + c_sub;
        int c = ct * 32 + c_loc;
        const float* xb = x + ((size_t)(b * CIN + c)) * NPIX;
        const float* wp1 = w1 + c * 9;
        const float* wp2 = w2 + c * 9;
        float a1a = 0.f, a1b = 0.f, a2a = 0.f, a2b = 0.f;
#pragma unroll
        for (int kh = 0; kh < 3; kh++) {
            int hh = h + kh - 1;
            if (hh < 0 || hh >= WWID) continue;
            const float* row = xb + hh * WWID;
            float xv0 = (w - 1 >= 0)    ? row[w - 1] : 0.f;
            float xv1 = row[w];
            float xv2 = row[w + 1];
            float xv3 = (w + 2 < WWID)  ? row[w + 2] : 0.f;
            float c10 = wp1[kh * 3 + 0], c11 = wp1[kh * 3 + 1], c12 = wp1[kh * 3 + 2];
            float c20 = wp2[kh * 3 + 0], c21 = wp2[kh * 3 + 1], c22 = wp2[kh * 3 + 2];
            a1a += xv0 * c10 + xv1 * c11 + xv2 * c12;
            a1b += xv1 * c10 + xv2 * c11 + xv3 * c12;
            a2a += xv0 * c20 + xv1 * c21 + xv2 * c22;
            a2b += xv1 * c20 + xv2 * c21 + xv3 * c22;
        }
        float inv1 = g1[c] * rsqrtf(v1[c] + EPS_F);
        float inv2 = g2[c] * rsqrtf(v2[c] + EPS_F);
        float ad1 = b1[c] - m1[c] * inv1;
        float ad2 = b2[c] - m2[c] * inv2;
        s1[c_loc][p2 * 2]     = a1a * inv1 + ad1;
        s1[c_loc][p2 * 2 + 1] = a1b * inv1 + ad1;
        s2[c_loc][p2 * 2]     = a2a * inv2 + ad2;
        s2[c_loc][p2 * 2 + 1] = a2b * inv2 + ad2;
    }
    __syncthreads();

#pragma unroll
    for (int i = 0; i < 2; i++) {
        int idx = tid + i * 256;
        int pp  = idx >> 3;
        int cq  = idx & 7;
        size_t base = ((size_t)(b * NPIX + pt * 64 + pp)) * CIN + ct * 32 + cq * 4;
        __half2 q0 = __floats2half2_rn(s1[cq*4+0][pp], s1[cq*4+1][pp]);
        __half2 q1 = __floats2half2_rn(s1[cq*4+2][pp], s1[cq*4+3][pp]);
        __half2 k0 = __floats2half2_rn(s2[cq*4+0][pp], s2[cq*4+1][pp]);
        __half2 k1 = __floats2half2_rn(s2[cq*4+2][pp], s2[cq*4+3][pp]);
        *(__half2*)(g_yq_h  + base)     = q0;
        *(__half2*)(g_yq_h  + base + 2) = q1;
        *(__half2*)(g_ykv_h + base)     = k0;
        *(__half2*)(g_ykv_h + base + 2) = k1;
    }
}

// ---------------------------------------------------------------------------
// 2) fp16 mma.sync GEMM body, 3-stage cp.async pipeline, ldmatrix fragments.
//    C[m][n] = sum_k A[m][k] * B[n][k], fp32 accum.
//    MODE 0: fp16 output to C[m*BP + n].  MODE 1: fp32 NCHW scatter + bias.
// ---------------------------------------------------------------------------
#define KTILE   32                        // halves per k-tile
#define SROW_H  40                        // halves per SMEM row (80B stride)
#define TILE_H  (128 * SROW_H)            // halves per operand tile
#define NSTAGE  3
#define STAGE_BYTES (2 * TILE_H * 2)      // A+B per stage
#define SMEM_GEMM_BYTES (NSTAGE * STAGE_BYTES)

template<int MODE>
__device__ __forceinline__ void gemm_body(
    __half* smem, const __half* __restrict__ A, const __half* __restrict__ Bm,
    void* __restrict__ Cv, int Kd, const float* __restrict__ bias, int m0, int n0)
{
    int tid = threadIdx.x;
    int wid = tid >> 5;
    int lane = tid & 31;
    int grp = lane >> 2;
    int qid = lane & 3;
    int warp_m = wid & 1;
    int warp_n = wid >> 1;
    int KT = Kd / KTILE;

    uint32_t smem_b = smem_u32(smem);

    auto load_tile = [&](int kt, int stage) {
        int k0 = kt * KTILE;
        uint32_t dA = smem_b + (uint32_t)stage * STAGE_BYTES;
        uint32_t dB = dA + TILE_H * 2;
#pragma unroll
        for (int i = 0; i < 2; i++) {
            int idx = tid + i * 256;
            int row = idx >> 2, q = idx & 3;
            cp_async16(dA + (uint32_t)(row * SROW_H + q * 8) * 2,
                       A + (size_t)(m0 + row) * Kd + k0 + q * 8);
        }
#pragma unroll
        for (int i = 0; i < 2; i++) {
            int idx = tid + i * 256;
            int row = idx >> 2, q = idx & 3;
            cp_async16(dB + (uint32_t)(row * SROW_H + q * 8) * 2,
                       Bm + (size_t)(n0 + row) * Kd + k0 + q * 8);
        }
    };

    float acc[4][4][4];
#pragma unroll
    for (int mt = 0; mt < 4; mt++)
#pragma unroll
        for (int nt = 0; nt < 4; nt++)
#pragma unroll
            for (int r = 0; r < 4; r++) acc[mt][nt][r] = 0.f;

    load_tile(0, 0);
    CP_COMMIT();
    load_tile(1, 1);
    CP_COMMIT();

    int rsel = (lane & 7) + ((lane >> 3) & 1) * 8;
    int csel = (lane >> 4) * 8;

    int stage = 0;
    for (int kt = 0; kt < KT; kt++) {
        CP_WAIT(1);
        __syncthreads();

        uint32_t As_u = smem_b + (uint32_t)stage * STAGE_BYTES;
        uint32_t Bs_u = As_u + TILE_H * 2;

#pragma unroll
        for (int ks = 0; ks < 2; ks++) {
            int col = ks * 16 + csel;
            uint32_t afr[4][4], bfr[4][2];
#pragma unroll
            for (int mt = 0; mt < 4; mt++) {
                uint32_t addr = As_u +
                    (uint32_t)((warp_m * 64 + mt * 16 + rsel) * SROW_H + col) * 2;
                ldsm_x4(afr[mt][0], afr[mt][1], afr[mt][2], afr[mt][3], addr);
            }
#pragma unroll
            for (int p = 0; p < 2; p++) {
                uint32_t addr = Bs_u +
                    (uint32_t)((warp_n * 32 + p * 16 + rsel) * SROW_H + col) * 2;
                uint32_t b0, b1, b2, b3;
                ldsm_x4(b0, b1, b2, b3, addr);
                bfr[p*2  ][0] = b0; bfr[p*2+1][0] = b1;
                bfr[p*2  ][1] = b2; bfr[p*2+1][1] = b3;
            }
#pragma unroll
            for (int mt = 0; mt < 4; mt++)
#pragma unroll
                for (int nt = 0; nt < 4; nt++)
                    mma_f16(acc[mt][nt], afr[mt], bfr[nt]);
        }

        if (kt + 2 < KT) {
            int nstage = stage + 2; if (nstage >= NSTAGE) nstage -= NSTAGE;
            load_tile(kt + 2, nstage);
        }
        CP_COMMIT();
        stage = (stage + 1 == NSTAGE) ? 0 : stage + 1;
    }

    // Epilogue
#pragma unroll
    for (int mt = 0; mt < 4; mt++) {
        int r0 = m0 + warp_m * 64 + mt * 16 + grp;
        int r1 = r0 + 8;
        float bs0 = (MODE == 1) ? bias[r0] : 0.f;
        float bs1 = (MODE == 1) ? bias[r1] : 0.f;
#pragma unroll
        for (int nt = 0; nt < 4; nt++) {
            int n = n0 + warp_n * 32 + nt * 8 + qid * 2;
            float* a4 = acc[mt][nt];
            if (MODE == 0) {
                __half* Ch = (__half*)Cv;
                *(__half2*)(Ch + (size_t)r0 * BP + n) = __floats2half2_rn(a4[0], a4[1]);
                *(__half2*)(Ch + (size_t)r1 * BP + n) = __floats2half2_rn(a4[2], a4[3]);
            } else {
                float* C = (float*)Cv;
                int bb = n / NPIX, p = n - bb * NPIX;
                *(float2*)(C + ((size_t)bb * CIN + r0) * NPIX + p) =
                    make_float2(a4[0] + bs0, a4[1] + bs0);
                *(float2*)(C + ((size_t)bb * CIN + r1) * NPIX + p) =
                    make_float2(a4[2] + bs1, a4[3] + bs1);
            }
        }
    }
}

// Merged q + kv projection: pointer-select, then ONE gemm_body call site.
__global__ void __launch_bounds__(256, 2) gemm_qkv()
{
    extern __shared__ __half smem[];
    int y = blockIdx.y;
    const __half* A;
    const __half* Bm;
    __half* C;
    int m0;
    if (y < 4) { A = g_wq_h;  Bm = g_yq_h;  C = g_q_h;  m0 = y * 128; }
    else       { A = g_wkv_h; Bm = g_ykv_h; C = g_kv_h; m0 = (y - 4) * 128; }
    gemm_body<0>(smem, A, Bm, C, CIN, nullptr, m0, blockIdx.x * 128);
}

// Output projection GEMM (+bias, NCHW scatter)
__global__ void __launch_bounds__(256, 2) gemm_out(float* __restrict__ C,
                                                   const float* __restrict__ bias)
{
    extern __shared__ __half smem[];
    gemm_body<1>(smem, g_wo_h, g_att_h, C, INNER, bias, blockIdx.y * 128, blockIdx.x * 128);
}

// ---------------------------------------------------------------------------
// 3) diag: each thread computes 2 adjacent pixels via half2 loads
// ---------------------------------------------------------------------------
__global__ void diag_kernel()
{
    int idx = blockIdx.x * blockDim.x + threadIdx.x;   // over NBH * NPIX/2
    int n2  = idx % (NPIX / 2);
    int bh  = idx / (NPIX / 2);
    int b = bh >> 3, h = bh & 7;
    int n = n2 * 2;
    size_t base = (size_t)b * NPIX + n;
    float s0 = 0.f, s1 = 0.f;
#pragma unroll 8
    for (int d = 0; d < DH; d++) {
        float2 qf = __half22float2(*(const __half2*)(g_q_h  + (size_t)(h * DH + d) * BP + base));
        float2 kf = __half22float2(*(const __half2*)(g_kv_h + (size_t)(h * DH + d) * BP + base));
        s0 += qf.x * kf.x;
        s1 += qf.y * kf.y;
    }
    g_diag[bh * NPIX + n]     = s0 * SCALE_F;
    g_diag[bh * NPIX + n + 1] = s1 * SCALE_F;
}

__global__ void reduce_diag1()
{
    __shared__ float sm[256];
    float s = 0.f;
    for (int i = blockIdx.x * 256 + threadIdx.x; i < NBH * NPIX; i += 256 * 256)
        s += g_diag[i];
    sm[threadIdx.x] = s;
    __syncthreads();
    for (int st = 128; st > 0; st >>= 1) {
        if (threadIdx.x < st) sm[threadIdx.x] += sm[threadIdx.x + st];
        __syncthreads();
    }
    if (threadIdx.x == 0) g_red[blockIdx.x] = sm[0];
}
__global__ void reduce_diag2()
{
    __shared__ float sm[256];
    sm[threadIdx.x] = g_red[threadIdx.x];
    __syncthreads();
    for (int st = 128; st > 0; st >>= 1) {
        if (threadIdx.x < st) sm[threadIdx.x] += sm[threadIdx.x + st];
        __syncthreads();
    }
    if (threadIdx.x == 0) g_m0[0] = sm[0];
}

// ---------------------------------------------------------------------------
// 4) ktv partials (grid NSPLIT x 64) + reduce; half2 global loads, fp32 accum
// ---------------------------------------------------------------------------
__global__ void ktv_partial()
{
    __shared__ float Ks[32][65];
    __shared__ float Vs[32][65];
    int split = blockIdx.x;
    int bh = blockIdx.y;
    int b = bh >> 3, h = bh & 7;
    int tid = threadIdx.x;
    int ty = tid >> 4, tx = tid & 15;

    float acc[4][4];
#pragma unroll
    for (int i = 0; i < 4; i++)
#pragma unroll
        for (int j = 0; j < 4; j++) acc[i][j] = 0.f;

    size_t base = (size_t)b * NPIX;
    int n_start = split * (NPIX / NSPLIT);

    for (int n0 = n_start; n0 < n_start + (NPIX / NSPLIT); n0 += 32) {
#pragma unroll
        for (int l = 0; l < 4; l++) {
            int e  = tid + l * 256;       // 0..1023
            int d  = e >> 4;              // 0..63
            int nn = (e & 15) * 2;        // 0,2,..30
            float2 kf = __half22float2(*(const __half2*)(g_kv_h + (size_t)(h * DH + d) * BP + base + n0 + nn));
            float2 vf = __half22float2(*(const __half2*)(g_kv_h + (size_t)(INNER + h * DH + d) * BP + base + n0 + nn));
            Ks[nn][d] = kf.x;  Ks[nn + 1][d] = kf.y;
            Vs[nn][d] = vf.x;  Vs[nn + 1][d] = vf.y;
        }
        __syncthreads();
#pragma unroll
        for (int nn = 0; nn < 32; nn++) {
            float a[4], bb[4];
#pragma unroll
            for (int i = 0; i < 4; i++) a[i]  = Ks[nn][ty * 4 + i];
#pragma unroll
            for (int j = 0; j < 4; j++) bb[j] = Vs[nn][tx * 4 + j];
#pragma unroll
            for (int i = 0; i < 4; i++)
#pragma unroll
                for (int j = 0; j < 4; j++) acc[i][j] += a[i] * bb[j];
        }
        __syncthreads();
    }
    float* dst = g_ktvp + ((size_t)(split * NBH + bh)) * (DH * DH);
#pragma unroll
    for (int i = 0; i < 4; i++)
#pragma unroll
        for (int j = 0; j < 4; j++)
            dst[(ty * 4 + i) * DH + tx * 4 + j] = acc[i][j];
}

__global__ void ktv_reduce()
{
    int idx = blockIdx.x * blockDim.x + threadIdx.x;
    if (idx >= NBH * DH * DH) return;
    float s = 0.f;
#pragma unroll
    for (int sp = 0; sp < NSPLIT; sp++)
        s += g_ktvp[(size_t)sp * (NBH * DH * DH) + idx];
    g_ktv[idx] = s;
}

// ---------------------------------------------------------------------------
// 5) att_out: 64 pixels per block, each thread handles 2 pixels x 8 e values.
// ---------------------------------------------------------------------------
__global__ void att_out_kernel()
{
    __shared__ float ktv_s[DH * DH];
    int bh = blockIdx.y;
    int b = bh >> 3, h = bh & 7;

    for (int i = threadIdx.x; i < DH * DH; i += 256)
        ktv_s[i] = g_ktv[bh * (DH * DH) + i];
    __syncthreads();

    float m0 = g_m0[0];
    int pn = threadIdx.x & 31;               // pixel pair 0..31
    int eg = threadIdx.x >> 5;                // 0..7
    int n = blockIdx.x * 64 + pn * 2;
    size_t base = (size_t)b * NPIX + n;

    float acc0[8], acc1[8];
#pragma unroll
    for (int j = 0; j < 8; j++) { acc0[j] = 0.f; acc1[j] = 0.f; }

#pragma unroll 4
    for (int d = 0; d < DH; d++) {
        float2 qf = __half22float2(*(const __half2*)(g_q_h + (size_t)(h * DH + d) * BP + base));
        const float* kv = ktv_s + d * DH + eg * 8;
#pragma unroll
        for (int j = 0; j < 8; j++) {
            acc0[j] += qf.x * kv[j];
            acc1[j] += qf.y * kv[j];
        }
    }

    float c0 = m0 - g_diag[bh * NPIX + n];
    float c1 = m0 - g_diag[bh * NPIX + n + 1];
    __half out0[8], out1[8];
#pragma unroll
    for (int j = 0; j < 8; j++) {
        int e = eg * 8 + j;
        float2 vf = __half22float2(*(const __half2*)(g_kv_h + (size_t)(INNER + h * DH + e) * BP + base));
        out0[j] = __float2half_rn(SCALE_F * acc0[j] + c0 * vf.x);
        out1[j] = __float2half_rn(SCALE_F * acc1[j] + c1 * vf.y);
    }
    __half2* d0 = (__half2*)(g_att_h + base * INNER + h * DH + eg * 8);
    __half2* d1 = (__half2*)(g_att_h + (base + 1) * INNER + h * DH + eg * 8);
#pragma unroll
    for (int j = 0; j < 4; j++) {
        d0[j] = __halves2half2(out0[j*2], out0[j*2+1]);
        d1[j] = __halves2half2(out1[j*2], out1[j*2+1]);
    }
}

// ---------------------------------------------------------------------------
// Launch
// ---------------------------------------------------------------------------
extern "C" void kernel_launch(void* const* d_in, const int* in_sizes, int n_in,
                              void* d_out, int out_size)
{
    const float* x       = (const float*)d_in[0];
    const float* wq_dw   = (const float*)d_in[1];
    const float* wq_g    = (const float*)d_in[2];
    const float* wq_b    = (const float*)d_in[3];
    const float* wq_m    = (const float*)d_in[4];
    const float* wq_v    = (const float*)d_in[5];
    const float* wq_pw   = (const float*)d_in[6];
    const float* wkv_dw  = (const float*)d_in[7];
    const float* wkv_g   = (const float*)d_in[8];
    const float* wkv_b   = (const float*)d_in[9];
    const float* wkv_m   = (const float*)d_in[10];
    const float* wkv_v   = (const float*)d_in[11];
    const float* wkv_pw  = (const float*)d_in[12];
    const float* wo      = (const float*)d_in[13];
    const float* bo      = (const float*)d_in[14];
    float* out = (float*)d_out;

    cudaFuncSetAttribute(gemm_qkv, cudaFuncAttributeMaxDynamicSharedMemorySize, SMEM_GEMM_BYTES);
    cudaFuncSetAttribute(gemm_out, cudaFuncAttributeMaxDynamicSharedMemorySize, SMEM_GEMM_BYTES);

    // 0) weight conversion to fp16
    cvt_weights_kernel<<<(NW1 + NW2 + NW3 + 255) / 256, 256>>>(wq_pw, wkv_pw, wo);

    // 1) depthwise conv + BN (pixel-pair, transposed [n][c] fp16 output)
    dwconv_bn_kernel<<<dim3(49, 12, 8), 256>>>(
        x, wq_dw, wq_g, wq_b, wq_m, wq_v,
           wkv_dw, wkv_g, wkv_b, wkv_m, wkv_v);

    // 2) q + kv projections, single tensor-core launch (pointer-select)
    gemm_qkv<<<dim3(196, 12), 256, SMEM_GEMM_BYTES>>>();

    // 3) attention middle (half2 loads, fp32 accumulate)
    diag_kernel<<<(NBH * NPIX / 2) / 256, 256>>>();
    reduce_diag1<<<256, 256>>>();
    reduce_diag2<<<1, 256>>>();
    ktv_partial<<<dim3(NSPLIT, NBH), 256>>>();
    ktv_reduce<<<(NBH * DH * DH) / 256, 256>>>();
    att_out_kernel<<<dim3(NPIX / 64, NBH), 256>>>();

    // 4) output projection (+bias, NCHW scatter)
    gemm_out<<<dim3(196, 3), 256, SMEM_GEMM_BYTES>>>(out, bo);
}

// round 14
// speedup vs baseline: 1.6220x; 1.1479x over previous
#include <cuda_runtime.h>
#include <cuda_fp16.h>
#include <cstdint>

// Problem constants
#define BATCH   8
#define CIN     384
#define NPIX    3136           // 56*56
#define WWID    56
#define BP      25088          // BATCH*NPIX
#define INNER   512
#define KVOUT   1024
#define HEADS   8
#define DH      64
#define NBH     64
#define SCALE_F 0.125f
#define EPS_F   1e-5f
#define NSPLIT  7

// ---------------------------------------------------------------------------
// Scratch (device globals)
// ---------------------------------------------------------------------------
__device__ __align__(16) __half g_yq_h [(size_t)BP * CIN];   // dwconv out, q path  [n][c]
__device__ __align__(16) __half g_ykv_h[(size_t)BP * CIN];   // dwconv out, kv path [n][c]
__device__ __align__(16) __half g_q_h [(size_t)INNER * BP];  // q   [m][n] fp16
__device__ __align__(16) __half g_kv_h[(size_t)KVOUT * BP];  // k|v [m][n] fp16
__device__ __align__(16) __half g_att_h[(size_t)BP * INNER]; // attention out [n][o]
__device__ __align__(16) __half g_wq_h [INNER * CIN];        // fp16 weights
__device__ __align__(16) __half g_wkv_h[KVOUT * CIN];
__device__ __align__(16) __half g_wo_h [CIN * INNER];
__device__ float g_diag[NBH * NPIX];
__device__ float g_ktvp[NSPLIT * NBH * DH * DH];
__device__ float g_ktv [NBH * DH * DH];
__device__ float g_red[256];
__device__ float g_m0[1];

// ---------------------------------------------------------------------------
// Helpers
// ---------------------------------------------------------------------------
__device__ __forceinline__ uint32_t smem_u32(const void* p) {
    uint32_t a;
    asm("{ .reg .u64 t; cvta.to.shared.u64 t, %1; cvt.u32.u64 %0, t; }" : "=r"(a) : "l"(p));
    return a;
}
__device__ __forceinline__ void cp_async16(uint32_t dst, const void* src) {
    asm volatile("cp.async.cg.shared.global [%0], [%1], 16;" :: "r"(dst), "l"(src));
}
#define CP_COMMIT() asm volatile("cp.async.commit_group;" ::: "memory")
#define CP_WAIT(N)  asm volatile("cp.async.wait_group %0;" :: "n"(N) : "memory")

__device__ __forceinline__ void mma_f16(float* c, const uint32_t* a, const uint32_t* b) {
    asm volatile(
        "mma.sync.aligned.m16n8k16.row.col.f32.f16.f16.f32 "
        "{%0,%1,%2,%3}, {%4,%5,%6,%7}, {%8,%9}, {%0,%1,%2,%3};"
        : "+f"(c[0]), "+f"(c[1]), "+f"(c[2]), "+f"(c[3])
        : "r"(a[0]), "r"(a[1]), "r"(a[2]), "r"(a[3]), "r"(b[0]), "r"(b[1]));
}
__device__ __forceinline__ void ldsm_x4(uint32_t& r0, uint32_t& r1, uint32_t& r2, uint32_t& r3,
                                        uint32_t addr) {
    asm volatile("ldmatrix.sync.aligned.m8n8.x4.shared.b16 {%0,%1,%2,%3}, [%4];"
                 : "=r"(r0), "=r"(r1), "=r"(r2), "=r"(r3) : "r"(addr));
}

// ---------------------------------------------------------------------------
// 0) Weight conversion (fp32 -> fp16), all three weights in one launch
// ---------------------------------------------------------------------------
#define NW1 (INNER * CIN)
#define NW2 (KVOUT * CIN)
#define NW3 (CIN * INNER)
__global__ void cvt_weights_kernel(const float* __restrict__ s1, const float* __restrict__ s2,
                                   const float* __restrict__ s3)
{
    int i = blockIdx.x * 256 + threadIdx.x;
    if (i < NW1) {
        g_wq_h[i] = __float2half_rn(s1[i]);
    } else if (i < NW1 + NW2) {
        g_wkv_h[i - NW1] = __float2half_rn(s2[i - NW1]);
    } else if (i < NW1 + NW2 + NW3) {
        g_wo_h[i - NW1 - NW2] = __float2half_rn(s3[i - NW1 - NW2]);
    }
}

// ---------------------------------------------------------------------------
// 1) Depthwise 3x3 conv + BN, output TRANSPOSED [n][c] fp16.
//    Each thread computes 2 adjacent pixels x 4 channels (shared 3x4 window).
// ---------------------------------------------------------------------------
__global__ void dwconv_bn_kernel(
    const float* __restrict__ x,
    const float* __restrict__ w1, const float* __restrict__ g1, const float* __restrict__ b1,
    const float* __restrict__ m1, const float* __restrict__ v1,
    const float* __restrict__ w2, const float* __restrict__ g2, const float* __restrict__ b2,
    const float* __restrict__ m2, const float* __restrict__ v2)
{
    __shared__ float s1[32][65];
    __shared__ float s2[32][65];
    int b  = blockIdx.z;
    int ct = blockIdx.y;     // 12 channel tiles of 32
    int pt = blockIdx.x;     // 49 pixel tiles of 64
    int tid = threadIdx.x;
    int p2    = tid & 31;    // pixel pair 0..31
    int c_sub = tid >> 5;    // 0..7
    int p = pt * 64 + p2 * 2;
    int h = p / WWID, w = p % WWID;   // p even -> both pixels in same row

#pragma unroll
    for (int i = 0; i < 4; i++) {
        int c_loc = i * 8 + c_sub;
        int c = ct * 32 + c_loc;
        const float* xb = x + ((size_t)(b * CIN + c)) * NPIX;
        const float* wp1 = w1 + c * 9;
        const float* wp2 = w2 + c * 9;
        float a1a = 0.f, a1b = 0.f, a2a = 0.f, a2b = 0.f;
#pragma unroll
        for (int kh = 0; kh < 3; kh++) {
            int hh = h + kh - 1;
            if (hh < 0 || hh >= WWID) continue;
            const float* row = xb + hh * WWID;
            float xv0 = (w - 1 >= 0)    ? row[w - 1] : 0.f;
            float xv1 = row[w];
            float xv2 = row[w + 1];
            float xv3 = (w + 2 < WWID)  ? row[w + 2] : 0.f;
            float c10 = wp1[kh * 3 + 0], c11 = wp1[kh * 3 + 1], c12 = wp1[kh * 3 + 2];
            float c20 = wp2[kh * 3 + 0], c21 = wp2[kh * 3 + 1], c22 = wp2[kh * 3 + 2];
            a1a += xv0 * c10 + xv1 * c11 + xv2 * c12;
            a1b += xv1 * c10 + xv2 * c11 + xv3 * c12;
            a2a += xv0 * c20 + xv1 * c21 + xv2 * c22;
            a2b += xv1 * c20 + xv2 * c21 + xv3 * c22;
        }
        float inv1 = g1[c] * rsqrtf(v1[c] + EPS_F);
        float inv2 = g2[c] * rsqrtf(v2[c] + EPS_F);
        float ad1 = b1[c] - m1[c] * inv1;
        float ad2 = b2[c] - m2[c] * inv2;
        s1[c_loc][p2 * 2]     = a1a * inv1 + ad1;
        s1[c_loc][p2 * 2 + 1] = a1b * inv1 + ad1;
        s2[c_loc][p2 * 2]     = a2a * inv2 + ad2;
        s2[c_loc][p2 * 2 + 1] = a2b * inv2 + ad2;
    }
    __syncthreads();

#pragma unroll
    for (int i = 0; i < 2; i++) {
        int idx = tid + i * 256;
        int pp  = idx >> 3;
        int cq  = idx & 7;
        size_t base = ((size_t)(b * NPIX + pt * 64 + pp)) * CIN + ct * 32 + cq * 4;
        __half2 q0 = __floats2half2_rn(s1[cq*4+0][pp], s1[cq*4+1][pp]);
        __half2 q1 = __floats2half2_rn(s1[cq*4+2][pp], s1[cq*4+3][pp]);
        __half2 k0 = __floats2half2_rn(s2[cq*4+0][pp], s2[cq*4+1][pp]);
        __half2 k1 = __floats2half2_rn(s2[cq*4+2][pp], s2[cq*4+3][pp]);
        *(__half2*)(g_yq_h  + base)     = q0;
        *(__half2*)(g_yq_h  + base + 2) = q1;
        *(__half2*)(g_ykv_h + base)     = k0;
        *(__half2*)(g_ykv_h + base + 2) = k1;
    }
}

// ---------------------------------------------------------------------------
// 2) fp16 mma.sync GEMM body, 3-stage cp.async pipeline, ldmatrix fragments.
//    C[m][n] = sum_k A[m][k] * B[n][k], fp32 accum.
//    MODE 0: fp16 output to C[m*BP + n].  MODE 1: fp32 NCHW scatter + bias.
// ---------------------------------------------------------------------------
#define KTILE   32                        // halves per k-tile
#define SROW_H  40                        // halves per SMEM row (80B stride)
#define TILE_H  (128 * SROW_H)            // halves per operand tile
#define NSTAGE  3
#define STAGE_BYTES (2 * TILE_H * 2)      // A+B per stage
#define SMEM_GEMM_BYTES (NSTAGE * STAGE_BYTES)

template<int MODE>
__device__ __forceinline__ void gemm_body(
    __half* smem, const __half* __restrict__ A, const __half* __restrict__ Bm,
    void* __restrict__ Cv, int Kd, const float* __restrict__ bias, int m0, int n0)
{
    int tid = threadIdx.x;
    int wid = tid >> 5;
    int lane = tid & 31;
    int grp = lane >> 2;
    int qid = lane & 3;
    int warp_m = wid & 1;
    int warp_n = wid >> 1;
    int KT = Kd / KTILE;

    uint32_t smem_b = smem_u32(smem);

    auto load_tile = [&](int kt, int stage) {
        int k0 = kt * KTILE;
        uint32_t dA = smem_b + (uint32_t)stage * STAGE_BYTES;
        uint32_t dB = dA + TILE_H * 2;
#pragma unroll
        for (int i = 0; i < 2; i++) {
            int idx = tid + i * 256;
            int row = idx >> 2, q = idx & 3;
            cp_async16(dA + (uint32_t)(row * SROW_H + q * 8) * 2,
                       A + (size_t)(m0 + row) * Kd + k0 + q * 8);
        }
#pragma unroll
        for (int i = 0; i < 2; i++) {
            int idx = tid + i * 256;
            int row = idx >> 2, q = idx & 3;
            cp_async16(dB + (uint32_t)(row * SROW_H + q * 8) * 2,
                       Bm + (size_t)(n0 + row) * Kd + k0 + q * 8);
        }
    };

    float acc[4][4][4];
#pragma unroll
    for (int mt = 0; mt < 4; mt++)
#pragma unroll
        for (int nt = 0; nt < 4; nt++)
#pragma unroll
            for (int r = 0; r < 4; r++) acc[mt][nt][r] = 0.f;

    load_tile(0, 0);
    CP_COMMIT();
    load_tile(1, 1);
    CP_COMMIT();

    int rsel = (lane & 7) + ((lane >> 3) & 1) * 8;
    int csel = (lane >> 4) * 8;

    int stage = 0;
    for (int kt = 0; kt < KT; kt++) {
        CP_WAIT(1);
        __syncthreads();

        uint32_t As_u = smem_b + (uint32_t)stage * STAGE_BYTES;
        uint32_t Bs_u = As_u + TILE_H * 2;

#pragma unroll
        for (int ks = 0; ks < 2; ks++) {
            int col = ks * 16 + csel;
            uint32_t afr[4][4], bfr[4][2];
#pragma unroll
            for (int mt = 0; mt < 4; mt++) {
                uint32_t addr = As_u +
                    (uint32_t)((warp_m * 64 + mt * 16 + rsel) * SROW_H + col) * 2;
                ldsm_x4(afr[mt][0], afr[mt][1], afr[mt][2], afr[mt][3], addr);
            }
#pragma unroll
            for (int p = 0; p < 2; p++) {
                uint32_t addr = Bs_u +
                    (uint32_t)((warp_n * 32 + p * 16 + rsel) * SROW_H + col) * 2;
                uint32_t b0, b1, b2, b3;
                ldsm_x4(b0, b1, b2, b3, addr);
                bfr[p*2  ][0] = b0; bfr[p*2+1][0] = b1;
                bfr[p*2  ][1] = b2; bfr[p*2+1][1] = b3;
            }
#pragma unroll
            for (int mt = 0; mt < 4; mt++)
#pragma unroll
                for (int nt = 0; nt < 4; nt++)
                    mma_f16(acc[mt][nt], afr[mt], bfr[nt]);
        }

        if (kt + 2 < KT) {
            int nstage = stage + 2; if (nstage >= NSTAGE) nstage -= NSTAGE;
            load_tile(kt + 2, nstage);
        }
        CP_COMMIT();
        stage = (stage + 1 == NSTAGE) ? 0 : stage + 1;
    }

    // Epilogue
#pragma unroll
    for (int mt = 0; mt < 4; mt++) {
        int r0 = m0 + warp_m * 64 + mt * 16 + grp;
        int r1 = r0 + 8;
        float bs0 = (MODE == 1) ? bias[r0] : 0.f;
        float bs1 = (MODE == 1) ? bias[r1] : 0.f;
#pragma unroll
        for (int nt = 0; nt < 4; nt++) {
            int n = n0 + warp_n * 32 + nt * 8 + qid * 2;
            float* a4 = acc[mt][nt];
            if (MODE == 0) {
                __half* Ch = (__half*)Cv;
                *(__half2*)(Ch + (size_t)r0 * BP + n) = __floats2half2_rn(a4[0], a4[1]);
                *(__half2*)(Ch + (size_t)r1 * BP + n) = __floats2half2_rn(a4[2], a4[3]);
            } else {
                float* C = (float*)Cv;
                int bb = n / NPIX, p = n - bb * NPIX;
                *(float2*)(C + ((size_t)bb * CIN + r0) * NPIX + p) =
                    make_float2(a4[0] + bs0, a4[1] + bs0);
                *(float2*)(C + ((size_t)bb * CIN + r1) * NPIX + p) =
                    make_float2(a4[2] + bs1, a4[3] + bs1);
            }
        }
    }
}

// Merged q + kv projection: pointer-select, then ONE gemm_body call site.
__global__ void __launch_bounds__(256, 2) gemm_qkv()
{
    extern __shared__ __half smem[];
    int y = blockIdx.y;
    const __half* A;
    const __half* Bm;
    __half* C;
    int m0;
    if (y < 4) { A = g_wq_h;  Bm = g_yq_h;  C = g_q_h;  m0 = y * 128; }
    else       { A = g_wkv_h; Bm = g_ykv_h; C = g_kv_h; m0 = (y - 4) * 128; }
    gemm_body<0>(smem, A, Bm, C, CIN, nullptr, m0, blockIdx.x * 128);
}

// Output projection GEMM (+bias, NCHW scatter)
__global__ void __launch_bounds__(256, 2) gemm_out(float* __restrict__ C,
                                                   const float* __restrict__ bias)
{
    extern __shared__ __half smem[];
    gemm_body<1>(smem, g_wo_h, g_att_h, C, INNER, bias, blockIdx.y * 128, blockIdx.x * 128);
}

// ---------------------------------------------------------------------------
// 3) diag: each thread computes 2 adjacent pixels via half2 loads
// ---------------------------------------------------------------------------
__global__ void diag_kernel()
{
    int idx = blockIdx.x * blockDim.x + threadIdx.x;   // over NBH * NPIX/2
    int n2  = idx % (NPIX / 2);
    int bh  = idx / (NPIX / 2);
    int b = bh >> 3, h = bh & 7;
    int n = n2 * 2;
    size_t base = (size_t)b * NPIX + n;
    float s0 = 0.f, s1 = 0.f;
#pragma unroll 8
    for (int d = 0; d < DH; d++) {
        float2 qf = __half22float2(*(const __half2*)(g_q_h  + (size_t)(h * DH + d) * BP + base));
        float2 kf = __half22float2(*(const __half2*)(g_kv_h + (size_t)(h * DH + d) * BP + base));
        s0 += qf.x * kf.x;
        s1 += qf.y * kf.y;
    }
    g_diag[bh * NPIX + n]     = s0 * SCALE_F;
    g_diag[bh * NPIX + n + 1] = s1 * SCALE_F;
}

__global__ void reduce_diag1()
{
    __shared__ float sm[256];
    float s = 0.f;
    for (int i = blockIdx.x * 256 + threadIdx.x; i < NBH * NPIX; i += 256 * 256)
        s += g_diag[i];
    sm[threadIdx.x] = s;
    __syncthreads();
    for (int st = 128; st > 0; st >>= 1) {
        if (threadIdx.x < st) sm[threadIdx.x] += sm[threadIdx.x + st];
        __syncthreads();
    }
    if (threadIdx.x == 0) g_red[blockIdx.x] = sm[0];
}
__global__ void reduce_diag2()
{
    __shared__ float sm[256];
    sm[threadIdx.x] = g_red[threadIdx.x];
    __syncthreads();
    for (int st = 128; st > 0; st >>= 1) {
        if (threadIdx.x < st) sm[threadIdx.x] += sm[threadIdx.x + st];
        __syncthreads();
    }
    if (threadIdx.x == 0) g_m0[0] = sm[0];
}

// ---------------------------------------------------------------------------
// 4) ktv partials on TENSOR CORES.
//    C[d][e] = sum_n K[d][n] * V[e][n]  per (split, bh).
//    K rows [d][n] = row-major A (k = n contiguous); V rows [e][n] = col-major B.
//    128 threads (4 warps): warp w computes d-rows [w*16, w*16+16) x all 64 e.
//    32-n chunks, cp.async double buffer, ldmatrix fragments, fp32 accum.
// ---------------------------------------------------------------------------
#define KTV_SROW 40
#define KTV_OP_H (64 * KTV_SROW)          // halves per operand buffer

__global__ void __launch_bounds__(128) ktv_partial()
{
    __shared__ __half sK[2 * KTV_OP_H];
    __shared__ __half sV[2 * KTV_OP_H];

    int split = blockIdx.x;
    int bh = blockIdx.y;
    int b = bh >> 3, h = bh & 7;
    int tid = threadIdx.x;
    int wid = tid >> 5;
    int lane = tid & 31;
    int grp = lane >> 2;
    int qid = lane & 3;

    uint32_t sK_u = smem_u32(sK);
    uint32_t sV_u = smem_u32(sV);

    size_t base = (size_t)b * NPIX + split * (NPIX / NSPLIT);
    const __half* Kg = g_kv_h + (size_t)(h * DH) * BP + base;
    const __half* Vg = g_kv_h + (size_t)(INNER + h * DH) * BP + base;

    // load one 64x32 chunk of K and V into stage s
    auto load_chunk = [&](int kt, int s) {
        int n0 = kt * 32;
        uint32_t dK = sK_u + (uint32_t)s * (KTV_OP_H * 2);
        uint32_t dV = sV_u + (uint32_t)s * (KTV_OP_H * 2);
#pragma unroll
        for (int i = 0; i < 2; i++) {
            int idx = tid + i * 128;        // 0..255
            int row = idx >> 2, q = idx & 3;
            cp_async16(dK + (uint32_t)(row * KTV_SROW + q * 8) * 2,
                       Kg + (size_t)row * BP + n0 + q * 8);
        }
#pragma unroll
        for (int i = 0; i < 2; i++) {
            int idx = tid + i * 128;
            int row = idx >> 2, q = idx & 3;
            cp_async16(dV + (uint32_t)(row * KTV_SROW + q * 8) * 2,
                       Vg + (size_t)row * BP + n0 + q * 8);
        }
    };

    float acc[8][4];
#pragma unroll
    for (int nt = 0; nt < 8; nt++)
#pragma unroll
        for (int r = 0; r < 4; r++) acc[nt][r] = 0.f;

    const int KT = (NPIX / NSPLIT) / 32;    // 14
    load_chunk(0, 0);
    CP_COMMIT();

    int rsel = (lane & 7) + ((lane >> 3) & 1) * 8;
    int csel = (lane >> 4) * 8;

    for (int kt = 0; kt < KT; kt++) {
        int buf = kt & 1;
        if (kt + 1 < KT) {
            load_chunk(kt + 1, buf ^ 1);
            CP_COMMIT();
            CP_WAIT(1);
        } else {
            CP_WAIT(0);
        }
        __syncthreads();

        uint32_t Kb = sK_u + (uint32_t)buf * (KTV_OP_H * 2);
        uint32_t Vb = sV_u + (uint32_t)buf * (KTV_OP_H * 2);

#pragma unroll
        for (int ks = 0; ks < 2; ks++) {
            int col = ks * 16 + csel;
            uint32_t afr[4];
            ldsm_x4(afr[0], afr[1], afr[2], afr[3],
                    Kb + (uint32_t)((wid * 16 + rsel) * KTV_SROW + col) * 2);
            uint32_t bfr[8][2];
#pragma unroll
            for (int p = 0; p < 4; p++) {
                uint32_t b0, b1, b2, b3;
                ldsm_x4(b0, b1, b2, b3,
                        Vb + (uint32_t)((p * 16 + rsel) * KTV_SROW + col) * 2);
                bfr[p*2  ][0] = b0; bfr[p*2+1][0] = b1;
                bfr[p*2  ][1] = b2; bfr[p*2+1][1] = b3;
            }
#pragma unroll
            for (int nt = 0; nt < 8; nt++)
                mma_f16(acc[nt], afr, bfr[nt]);
        }
        __syncthreads();
    }

    // Epilogue: fp32 store to g_ktvp[split][bh][d][e]
    float* dst = g_ktvp + ((size_t)(split * NBH + bh)) * (DH * DH);
    int d0 = wid * 16 + grp;
    int d1 = d0 + 8;
#pragma unroll
    for (int nt = 0; nt < 8; nt++) {
        int e = nt * 8 + qid * 2;
        *(float2*)(dst + d0 * DH + e) = make_float2(acc[nt][0], acc[nt][1]);
        *(float2*)(dst + d1 * DH + e) = make_float2(acc[nt][2], acc[nt][3]);
    }
}

__global__ void ktv_reduce()
{
    int idx = blockIdx.x * blockDim.x + threadIdx.x;
    if (idx >= NBH * DH * DH) return;
    float s = 0.f;
#pragma unroll
    for (int sp = 0; sp < NSPLIT; sp++)
        s += g_ktvp[(size_t)sp * (NBH * DH * DH) + idx];
    g_ktv[idx] = s;
}

// ---------------------------------------------------------------------------
// 5) att_out: 64 pixels per block, each thread handles 2 pixels x 8 e values.
// ---------------------------------------------------------------------------
__global__ void att_out_kernel()
{
    __shared__ float ktv_s[DH * DH];
    int bh = blockIdx.y;
    int b = bh >> 3, h = bh & 7;

    for (int i = threadIdx.x; i < DH * DH; i += 256)
        ktv_s[i] = g_ktv[bh * (DH * DH) + i];
    __syncthreads();

    float m0 = g_m0[0];
    int pn = threadIdx.x & 31;               // pixel pair 0..31
    int eg = threadIdx.x >> 5;                // 0..7
    int n = blockIdx.x * 64 + pn * 2;
    size_t base = (size_t)b * NPIX + n;

    float acc0[8], acc1[8];
#pragma unroll
    for (int j = 0; j < 8; j++) { acc0[j] = 0.f; acc1[j] = 0.f; }

#pragma unroll 4
    for (int d = 0; d < DH; d++) {
        float2 qf = __half22float2(*(const __half2*)(g_q_h + (size_t)(h * DH + d) * BP + base));
        const float* kv = ktv_s + d * DH + eg * 8;
#pragma unroll
        for (int j = 0; j < 8; j++) {
            acc0[j] += qf.x * kv[j];
            acc1[j] += qf.y * kv[j];
        }
    }

    float c0 = m0 - g_diag[bh * NPIX + n];
    float c1 = m0 - g_diag[bh * NPIX + n + 1];
    __half out0[8], out1[8];
#pragma unroll
    for (int j = 0; j < 8; j++) {
        int e = eg * 8 + j;
        float2 vf = __half22float2(*(const __half2*)(g_kv_h + (size_t)(INNER + h * DH + e) * BP + base));
        out0[j] = __float2half_rn(SCALE_F * acc0[j] + c0 * vf.x);
        out1[j] = __float2half_rn(SCALE_F * acc1[j] + c1 * vf.y);
    }
    __half2* d0 = (__half2*)(g_att_h + base * INNER + h * DH + eg * 8);
    __half2* d1 = (__half2*)(g_att_h + (base + 1) * INNER + h * DH + eg * 8);
#pragma unroll
    for (int j = 0; j < 4; j++) {
        d0[j] = __halves2half2(out0[j*2], out0[j*2+1]);
        d1[j] = __halves2half2(out1[j*2], out1[j*2+1]);
    }
}

// ---------------------------------------------------------------------------
// Launch
// ---------------------------------------------------------------------------
extern "C" void kernel_launch(void* const* d_in, const int* in_sizes, int n_in,
                              void* d_out, int out_size)
{
    const float* x       = (const float*)d_in[0];
    const float* wq_dw   = (const float*)d_in[1];
    const float* wq_g    = (const float*)d_in[2];
    const float* wq_b    = (const float*)d_in[3];
    const float* wq_m    = (const float*)d_in[4];
    const float* wq_v    = (const float*)d_in[5];
    const float* wq_pw   = (const float*)d_in[6];
    const float* wkv_dw  = (const float*)d_in[7];
    const float* wkv_g   = (const float*)d_in[8];
    const float* wkv_b   = (const float*)d_in[9];
    const float* wkv_m   = (const float*)d_in[10];
    const float* wkv_v   = (const float*)d_in[11];
    const float* wkv_pw  = (const float*)d_in[12];
    const float* wo      = (const float*)d_in[13];
    const float* bo      = (const float*)d_in[14];
    float* out = (float*)d_out;

    cudaFuncSetAttribute(gemm_qkv, cudaFuncAttributeMaxDynamicSharedMemorySize, SMEM_GEMM_BYTES);
    cudaFuncSetAttribute(gemm_out, cudaFuncAttributeMaxDynamicSharedMemorySize, SMEM_GEMM_BYTES);

    // 0) weight conversion to fp16
    cvt_weights_kernel<<<(NW1 + NW2 + NW3 + 255) / 256, 256>>>(wq_pw, wkv_pw, wo);

    // 1) depthwise conv + BN (pixel-pair, transposed [n][c] fp16 output)
    dwconv_bn_kernel<<<dim3(49, 12, 8), 256>>>(
        x, wq_dw, wq_g, wq_b, wq_m, wq_v,
           wkv_dw, wkv_g, wkv_b, wkv_m, wkv_v);

    // 2) q + kv projections, single tensor-core launch (pointer-select)
    gemm_qkv<<<dim3(196, 12), 256, SMEM_GEMM_BYTES>>>();

    // 3) attention middle
    diag_kernel<<<(NBH * NPIX / 2) / 256, 256>>>();
    reduce_diag1<<<256, 256>>>();
    reduce_diag2<<<1, 256>>>();
    ktv_partial<<<dim3(NSPLIT, NBH), 128>>>();
    ktv_reduce<<<(NBH * DH * DH) / 256, 256>>>();
    att_out_kernel<<<dim3(NPIX / 64, NBH), 256>>>();

    // 4) output projection (+bias, NCHW scatter)
    gemm_out<<<dim3(196, 3), 256, SMEM_GEMM_BYTES>>>(out, bo);
}

// round 15
// speedup vs baseline: 1.6749x; 1.0326x over previous
#include <cuda_runtime.h>
#include <cuda_fp16.h>
#include <cstdint>

// Problem constants
#define BATCH   8
#define CIN     384
#define NPIX    3136           // 56*56
#define WWID    56
#define BP      25088          // BATCH*NPIX
#define INNER   512
#define KVOUT   1024
#define HEADS   8
#define DH      64
#define NBH     64
#define SCALE_F 0.125f
#define EPS_F   1e-5f
#define NSPLIT  7

// ---------------------------------------------------------------------------
// Scratch (device globals)
// ---------------------------------------------------------------------------
__device__ __align__(16) __half g_yq_h [(size_t)BP * CIN];   // dwconv out, q path  [n][c]
__device__ __align__(16) __half g_ykv_h[(size_t)BP * CIN];   // dwconv out, kv path [n][c]
__device__ __align__(16) __half g_q_h [(size_t)INNER * BP];  // q   [m][n] fp16
__device__ __align__(16) __half g_kv_h[(size_t)KVOUT * BP];  // k|v [m][n] fp16
__device__ __align__(16) __half g_att_h[(size_t)BP * INNER]; // attention out [n][o]
__device__ __align__(16) __half g_wq_h [INNER * CIN];        // fp16 weights
__device__ __align__(16) __half g_wkv_h[KVOUT * CIN];
__device__ __align__(16) __half g_wo_h [CIN * INNER];
__device__ float g_diag[NBH * NPIX];
__device__ float g_ktvp[NSPLIT * NBH * DH * DH];
__device__ float g_ktv [NBH * DH * DH];
__device__ float g_red[512];
__device__ float g_m0[1];

// ---------------------------------------------------------------------------
// Helpers
// ---------------------------------------------------------------------------
__device__ __forceinline__ uint32_t smem_u32(const void* p) {
    uint32_t a;
    asm("{ .reg .u64 t; cvta.to.shared.u64 t, %1; cvt.u32.u64 %0, t; }" : "=r"(a) : "l"(p));
    return a;
}
__device__ __forceinline__ void cp_async16(uint32_t dst, const void* src) {
    asm volatile("cp.async.cg.shared.global [%0], [%1], 16;" :: "r"(dst), "l"(src));
}
#define CP_COMMIT() asm volatile("cp.async.commit_group;" ::: "memory")
#define CP_WAIT(N)  asm volatile("cp.async.wait_group %0;" :: "n"(N) : "memory")

__device__ __forceinline__ void mma_f16(float* c, const uint32_t* a, const uint32_t* b) {
    asm volatile(
        "mma.sync.aligned.m16n8k16.row.col.f32.f16.f16.f32 "
        "{%0,%1,%2,%3}, {%4,%5,%6,%7}, {%8,%9}, {%0,%1,%2,%3};"
        : "+f"(c[0]), "+f"(c[1]), "+f"(c[2]), "+f"(c[3])
        : "r"(a[0]), "r"(a[1]), "r"(a[2]), "r"(a[3]), "r"(b[0]), "r"(b[1]));
}
__device__ __forceinline__ void ldsm_x4(uint32_t& r0, uint32_t& r1, uint32_t& r2, uint32_t& r3,
                                        uint32_t addr) {
    asm volatile("ldmatrix.sync.aligned.m8n8.x4.shared.b16 {%0,%1,%2,%3}, [%4];"
                 : "=r"(r0), "=r"(r1), "=r"(r2), "=r"(r3) : "r"(addr));
}

// ---------------------------------------------------------------------------
// 0) Weight conversion (fp32 -> fp16), all three weights in one launch
// ---------------------------------------------------------------------------
#define NW1 (INNER * CIN)
#define NW2 (KVOUT * CIN)
#define NW3 (CIN * INNER)
__global__ void cvt_weights_kernel(const float* __restrict__ s1, const float* __restrict__ s2,
                                   const float* __restrict__ s3)
{
    int i = blockIdx.x * 256 + threadIdx.x;
    if (i < NW1) {
        g_wq_h[i] = __float2half_rn(s1[i]);
    } else if (i < NW1 + NW2) {
        g_wkv_h[i - NW1] = __float2half_rn(s2[i - NW1]);
    } else if (i < NW1 + NW2 + NW3) {
        g_wo_h[i - NW1 - NW2] = __float2half_rn(s3[i - NW1 - NW2]);
    }
}

// ---------------------------------------------------------------------------
// 1) Depthwise 3x3 conv + BN, output TRANSPOSED [n][c] fp16.
//    Each thread computes 2 adjacent pixels x 4 channels (shared 3x4 window).
// ---------------------------------------------------------------------------
__global__ void dwconv_bn_kernel(
    const float* __restrict__ x,
    const float* __restrict__ w1, const float* __restrict__ g1, const float* __restrict__ b1,
    const float* __restrict__ m1, const float* __restrict__ v1,
    const float* __restrict__ w2, const float* __restrict__ g2, const float* __restrict__ b2,
    const float* __restrict__ m2, const float* __restrict__ v2)
{
    __shared__ float s1[32][65];
    __shared__ float s2[32][65];
    int b  = blockIdx.z;
    int ct = blockIdx.y;     // 12 channel tiles of 32
    int pt = blockIdx.x;     // 49 pixel tiles of 64
    int tid = threadIdx.x;
    int p2    = tid & 31;    // pixel pair 0..31
    int c_sub = tid >> 5;    // 0..7
    int p = pt * 64 + p2 * 2;
    int h = p / WWID, w = p % WWID;   // p even -> both pixels in same row

#pragma unroll
    for (int i = 0; i < 4; i++) {
        int c_loc = i * 8 + c_sub;
        int c = ct * 32 + c_loc;
        const float* xb = x + ((size_t)(b * CIN + c)) * NPIX;
        const float* wp1 = w1 + c * 9;
        const float* wp2 = w2 + c * 9;
        float a1a = 0.f, a1b = 0.f, a2a = 0.f, a2b = 0.f;
#pragma unroll
        for (int kh = 0; kh < 3; kh++) {
            int hh = h + kh - 1;
            if (hh < 0 || hh >= WWID) continue;
            const float* row = xb + hh * WWID;
            float xv0 = (w - 1 >= 0)    ? row[w - 1] : 0.f;
            float xv1 = row[w];
            float xv2 = row[w + 1];
            float xv3 = (w + 2 < WWID)  ? row[w + 2] : 0.f;
            float c10 = wp1[kh * 3 + 0], c11 = wp1[kh * 3 + 1], c12 = wp1[kh * 3 + 2];
            float c20 = wp2[kh * 3 + 0], c21 = wp2[kh * 3 + 1], c22 = wp2[kh * 3 + 2];
            a1a += xv0 * c10 + xv1 * c11 + xv2 * c12;
            a1b += xv1 * c10 + xv2 * c11 + xv3 * c12;
            a2a += xv0 * c20 + xv1 * c21 + xv2 * c22;
            a2b += xv1 * c20 + xv2 * c21 + xv3 * c22;
        }
        float inv1 = g1[c] * rsqrtf(v1[c] + EPS_F);
        float inv2 = g2[c] * rsqrtf(v2[c] + EPS_F);
        float ad1 = b1[c] - m1[c] * inv1;
        float ad2 = b2[c] - m2[c] * inv2;
        s1[c_loc][p2 * 2]     = a1a * inv1 + ad1;
        s1[c_loc][p2 * 2 + 1] = a1b * inv1 + ad1;
        s2[c_loc][p2 * 2]     = a2a * inv2 + ad2;
        s2[c_loc][p2 * 2 + 1] = a2b * inv2 + ad2;
    }
    __syncthreads();

#pragma unroll
    for (int i = 0; i < 2; i++) {
        int idx = tid + i * 256;
        int pp  = idx >> 3;
        int cq  = idx & 7;
        size_t base = ((size_t)(b * NPIX + pt * 64 + pp)) * CIN + ct * 32 + cq * 4;
        __half2 q0 = __floats2half2_rn(s1[cq*4+0][pp], s1[cq*4+1][pp]);
        __half2 q1 = __floats2half2_rn(s1[cq*4+2][pp], s1[cq*4+3][pp]);
        __half2 k0 = __floats2half2_rn(s2[cq*4+0][pp], s2[cq*4+1][pp]);
        __half2 k1 = __floats2half2_rn(s2[cq*4+2][pp], s2[cq*4+3][pp]);
        *(__half2*)(g_yq_h  + base)     = q0;
        *(__half2*)(g_yq_h  + base + 2) = q1;
        *(__half2*)(g_ykv_h + base)     = k0;
        *(__half2*)(g_ykv_h + base + 2) = k1;
    }
}

// ---------------------------------------------------------------------------
// 2) fp16 mma.sync GEMM body, 3-stage cp.async pipeline, ldmatrix fragments.
//    K-tile 64 halves (halved barrier count).
//    C[m][n] = sum_k A[m][k] * B[n][k], fp32 accum.
//    MODE 0: fp16 output to C[m*BP + n].  MODE 1: fp32 NCHW scatter + bias.
// ---------------------------------------------------------------------------
#define KTILE   64                        // halves per k-tile
#define SROW_H  72                        // halves per SMEM row (144B stride; 36w = 4 mod 32 -> conflict-free)
#define TILE_H  (128 * SROW_H)            // halves per operand tile
#define NSTAGE  3
#define STAGE_BYTES (2 * TILE_H * 2)      // A+B per stage
#define SMEM_GEMM_BYTES (NSTAGE * STAGE_BYTES)

template<int MODE>
__device__ __forceinline__ void gemm_body(
    __half* smem, const __half* __restrict__ A, const __half* __restrict__ Bm,
    void* __restrict__ Cv, int Kd, const float* __restrict__ bias, int m0, int n0)
{
    int tid = threadIdx.x;
    int wid = tid >> 5;
    int lane = tid & 31;
    int grp = lane >> 2;
    int qid = lane & 3;
    int warp_m = wid & 1;
    int warp_n = wid >> 1;
    int KT = Kd / KTILE;

    uint32_t smem_b = smem_u32(smem);

    auto load_tile = [&](int kt, int stage) {
        int k0 = kt * KTILE;
        uint32_t dA = smem_b + (uint32_t)stage * STAGE_BYTES;
        uint32_t dB = dA + TILE_H * 2;
#pragma unroll
        for (int i = 0; i < 4; i++) {
            int idx = tid + i * 256;        // 0..1023: 128 rows x 8 chunks
            int row = idx >> 3, q = idx & 7;
            cp_async16(dA + (uint32_t)(row * SROW_H + q * 8) * 2,
                       A + (size_t)(m0 + row) * Kd + k0 + q * 8);
        }
#pragma unroll
        for (int i = 0; i < 4; i++) {
            int idx = tid + i * 256;
            int row = idx >> 3, q = idx & 7;
            cp_async16(dB + (uint32_t)(row * SROW_H + q * 8) * 2,
                       Bm + (size_t)(n0 + row) * Kd + k0 + q * 8);
        }
    };

    float acc[4][4][4];
#pragma unroll
    for (int mt = 0; mt < 4; mt++)
#pragma unroll
        for (int nt = 0; nt < 4; nt++)
#pragma unroll
            for (int r = 0; r < 4; r++) acc[mt][nt][r] = 0.f;

    load_tile(0, 0);
    CP_COMMIT();
    load_tile(1, 1);
    CP_COMMIT();

    int rsel = (lane & 7) + ((lane >> 3) & 1) * 8;
    int csel = (lane >> 4) * 8;

    int stage = 0;
    for (int kt = 0; kt < KT; kt++) {
        CP_WAIT(1);
        __syncthreads();

        uint32_t As_u = smem_b + (uint32_t)stage * STAGE_BYTES;
        uint32_t Bs_u = As_u + TILE_H * 2;

#pragma unroll
        for (int ks = 0; ks < 4; ks++) {     // 4 x k16 per 64-half tile
            int col = ks * 16 + csel;
            uint32_t afr[4][4], bfr[4][2];
#pragma unroll
            for (int mt = 0; mt < 4; mt++) {
                uint32_t addr = As_u +
                    (uint32_t)((warp_m * 64 + mt * 16 + rsel) * SROW_H + col) * 2;
                ldsm_x4(afr[mt][0], afr[mt][1], afr[mt][2], afr[mt][3], addr);
            }
#pragma unroll
            for (int p = 0; p < 2; p++) {
                uint32_t addr = Bs_u +
                    (uint32_t)((warp_n * 32 + p * 16 + rsel) * SROW_H + col) * 2;
                uint32_t b0, b1, b2, b3;
                ldsm_x4(b0, b1, b2, b3, addr);
                bfr[p*2  ][0] = b0; bfr[p*2+1][0] = b1;
                bfr[p*2  ][1] = b2; bfr[p*2+1][1] = b3;
            }
#pragma unroll
            for (int mt = 0; mt < 4; mt++)
#pragma unroll
                for (int nt = 0; nt < 4; nt++)
                    mma_f16(acc[mt][nt], afr[mt], bfr[nt]);
        }

        if (kt + 2 < KT) {
            int nstage = stage + 2; if (nstage >= NSTAGE) nstage -= NSTAGE;
            load_tile(kt + 2, nstage);
        }
        CP_COMMIT();
        stage = (stage + 1 == NSTAGE) ? 0 : stage + 1;
    }

    // Epilogue
#pragma unroll
    for (int mt = 0; mt < 4; mt++) {
        int r0 = m0 + warp_m * 64 + mt * 16 + grp;
        int r1 = r0 + 8;
        float bs0 = (MODE == 1) ? bias[r0] : 0.f;
        float bs1 = (MODE == 1) ? bias[r1] : 0.f;
#pragma unroll
        for (int nt = 0; nt < 4; nt++) {
            int n = n0 + warp_n * 32 + nt * 8 + qid * 2;
            float* a4 = acc[mt][nt];
            if (MODE == 0) {
                __half* Ch = (__half*)Cv;
                *(__half2*)(Ch + (size_t)r0 * BP + n) = __floats2half2_rn(a4[0], a4[1]);
                *(__half2*)(Ch + (size_t)r1 * BP + n) = __floats2half2_rn(a4[2], a4[3]);
            } else {
                float* C = (float*)Cv;
                int bb = n / NPIX, p = n - bb * NPIX;
                *(float2*)(C + ((size_t)bb * CIN + r0) * NPIX + p) =
                    make_float2(a4[0] + bs0, a4[1] + bs0);
                *(float2*)(C + ((size_t)bb * CIN + r1) * NPIX + p) =
                    make_float2(a4[2] + bs1, a4[3] + bs1);
            }
        }
    }
}

// Merged q + kv projection: pointer-select, then ONE gemm_body call site.
__global__ void __launch_bounds__(256, 2) gemm_qkv()
{
    extern __shared__ __half smem[];
    int y = blockIdx.y;
    const __half* A;
    const __half* Bm;
    __half* C;
    int m0;
    if (y < 4) { A = g_wq_h;  Bm = g_yq_h;  C = g_q_h;  m0 = y * 128; }
    else       { A = g_wkv_h; Bm = g_ykv_h; C = g_kv_h; m0 = (y - 4) * 128; }
    gemm_body<0>(smem, A, Bm, C, CIN, nullptr, m0, blockIdx.x * 128);
}

// Output projection GEMM (+bias, NCHW scatter)
__global__ void __launch_bounds__(256, 2) gemm_out(float* __restrict__ C,
                                                   const float* __restrict__ bias)
{
    extern __shared__ __half smem[];
    gemm_body<1>(smem, g_wo_h, g_att_h, C, INNER, bias, blockIdx.y * 128, blockIdx.x * 128);
}

// ---------------------------------------------------------------------------
// 3) diag + block partial sum (fused reduce pass 1)
// ---------------------------------------------------------------------------
__global__ void diag_kernel()
{
    __shared__ float sm[256];
    int tid = threadIdx.x;
    int idx = blockIdx.x * 256 + tid;                  // over NBH * NPIX/2
    int n2  = idx % (NPIX / 2);
    int bh  = idx / (NPIX / 2);
    int b = bh >> 3, h = bh & 7;
    int n = n2 * 2;
    size_t base = (size_t)b * NPIX + n;
    float s0 = 0.f, s1 = 0.f;
#pragma unroll 8
    for (int d = 0; d < DH; d++) {
        float2 qf = __half22float2(*(const __half2*)(g_q_h  + (size_t)(h * DH + d) * BP + base));
        float2 kf = __half22float2(*(const __half2*)(g_kv_h + (size_t)(h * DH + d) * BP + base));
        s0 += qf.x * kf.x;
        s1 += qf.y * kf.y;
    }
    s0 *= SCALE_F; s1 *= SCALE_F;
    g_diag[bh * NPIX + n]     = s0;
    g_diag[bh * NPIX + n + 1] = s1;

    sm[tid] = s0 + s1;
    __syncthreads();
    for (int st = 128; st > 0; st >>= 1) {
        if (tid < st) sm[tid] += sm[tid + st];
        __syncthreads();
    }
    if (tid == 0) g_red[blockIdx.x] = sm[0];
}

// reduce 392 block partials -> m0
__global__ void reduce_diag2()
{
    __shared__ float sm[256];
    int tid = threadIdx.x;
    float s = g_red[tid];
    if (tid + 256 < 392) s += g_red[tid + 256];
    sm[tid] = s;
    __syncthreads();
    for (int st = 128; st > 0; st >>= 1) {
        if (tid < st) sm[tid] += sm[tid + st];
        __syncthreads();
    }
    if (tid == 0) g_m0[0] = sm[0];
}

// ---------------------------------------------------------------------------
// 4) ktv partials on tensor cores (grid NSPLIT x 64), fp32 accum
// ---------------------------------------------------------------------------
#define KTV_SROW 40
#define KTV_OP_H (64 * KTV_SROW)          // halves per operand buffer

__global__ void __launch_bounds__(128) ktv_partial()
{
    __shared__ __half sK[2 * KTV_OP_H];
    __shared__ __half sV[2 * KTV_OP_H];

    int split = blockIdx.x;
    int bh = blockIdx.y;
    int b = bh >> 3, h = bh & 7;
    int tid = threadIdx.x;
    int wid = tid >> 5;
    int lane = tid & 31;
    int grp = lane >> 2;
    int qid = lane & 3;

    uint32_t sK_u = smem_u32(sK);
    uint32_t sV_u = smem_u32(sV);

    size_t base = (size_t)b * NPIX + split * (NPIX / NSPLIT);
    const __half* Kg = g_kv_h + (size_t)(h * DH) * BP + base;
    const __half* Vg = g_kv_h + (size_t)(INNER + h * DH) * BP + base;

    auto load_chunk = [&](int kt, int s) {
        int n0 = kt * 32;
        uint32_t dK = sK_u + (uint32_t)s * (KTV_OP_H * 2);
        uint32_t dV = sV_u + (uint32_t)s * (KTV_OP_H * 2);
#pragma unroll
        for (int i = 0; i < 2; i++) {
            int idx = tid + i * 128;
            int row = idx >> 2, q = idx & 3;
            cp_async16(dK + (uint32_t)(row * KTV_SROW + q * 8) * 2,
                       Kg + (size_t)row * BP + n0 + q * 8);
        }
#pragma unroll
        for (int i = 0; i < 2; i++) {
            int idx = tid + i * 128;
            int row = idx >> 2, q = idx & 3;
            cp_async16(dV + (uint32_t)(row * KTV_SROW + q * 8) * 2,
                       Vg + (size_t)row * BP + n0 + q * 8);
        }
    };

    float acc[8][4];
#pragma unroll
    for (int nt = 0; nt < 8; nt++)
#pragma unroll
        for (int r = 0; r < 4; r++) acc[nt][r] = 0.f;

    const int KT = (NPIX / NSPLIT) / 32;
    load_chunk(0, 0);
    CP_COMMIT();

    int rsel = (lane & 7) + ((lane >> 3) & 1) * 8;
    int csel = (lane >> 4) * 8;

    for (int kt = 0; kt < KT; kt++) {
        int buf = kt & 1;
        if (kt + 1 < KT) {
            load_chunk(kt + 1, buf ^ 1);
            CP_COMMIT();
            CP_WAIT(1);
        } else {
            CP_WAIT(0);
        }
        __syncthreads();

        uint32_t Kb = sK_u + (uint32_t)buf * (KTV_OP_H * 2);
        uint32_t Vb = sV_u + (uint32_t)buf * (KTV_OP_H * 2);

#pragma unroll
        for (int ks = 0; ks < 2; ks++) {
            int col = ks * 16 + csel;
            uint32_t afr[4];
            ldsm_x4(afr[0], afr[1], afr[2], afr[3],
                    Kb + (uint32_t)((wid * 16 + rsel) * KTV_SROW + col) * 2);
            uint32_t bfr[8][2];
#pragma unroll
            for (int p = 0; p < 4; p++) {
                uint32_t b0, b1, b2, b3;
                ldsm_x4(b0, b1, b2, b3,
                        Vb + (uint32_t)((p * 16 + rsel) * KTV_SROW + col) * 2);
                bfr[p*2  ][0] = b0; bfr[p*2+1][0] = b1;
                bfr[p*2  ][1] = b2; bfr[p*2+1][1] = b3;
            }
#pragma unroll
            for (int nt = 0; nt < 8; nt++)
                mma_f16(acc[nt], afr, bfr[nt]);
        }
        __syncthreads();
    }

    float* dst = g_ktvp + ((size_t)(split * NBH + bh)) * (DH * DH);
    int d0 = wid * 16 + grp;
    int d1 = d0 + 8;
#pragma unroll
    for (int nt = 0; nt < 8; nt++) {
        int e = nt * 8 + qid * 2;
        *(float2*)(dst + d0 * DH + e) = make_float2(acc[nt][0], acc[nt][1]);
        *(float2*)(dst + d1 * DH + e) = make_float2(acc[nt][2], acc[nt][3]);
    }
}

__global__ void ktv_reduce()
{
    int idx = blockIdx.x * blockDim.x + threadIdx.x;
    if (idx >= NBH * DH * DH) return;
    float s = 0.f;
#pragma unroll
    for (int sp = 0; sp < NSPLIT; sp++)
        s += g_ktvp[(size_t)sp * (NBH * DH * DH) + idx];
    g_ktv[idx] = s;
}

// ---------------------------------------------------------------------------
// 5) att_out: 64 pixels per block, each thread handles 2 pixels x 8 e values.
// ---------------------------------------------------------------------------
__global__ void att_out_kernel()
{
    __shared__ float ktv_s[DH * DH];
    int bh = blockIdx.y;
    int b = bh >> 3, h = bh & 7;

    for (int i = threadIdx.x; i < DH * DH; i += 256)
        ktv_s[i] = g_ktv[bh * (DH * DH) + i];
    __syncthreads();

    float m0 = g_m0[0];
    int pn = threadIdx.x & 31;
    int eg = threadIdx.x >> 5;
    int n = blockIdx.x * 64 + pn * 2;
    size_t base = (size_t)b * NPIX + n;

    float acc0[8], acc1[8];
#pragma unroll
    for (int j = 0; j < 8; j++) { acc0[j] = 0.f; acc1[j] = 0.f; }

#pragma unroll 4
    for (int d = 0; d < DH; d++) {
        float2 qf = __half22float2(*(const __half2*)(g_q_h + (size_t)(h * DH + d) * BP + base));
        const float* kv = ktv_s + d * DH + eg * 8;
#pragma unroll
        for (int j = 0; j < 8; j++) {
            acc0[j] += qf.x * kv[j];
            acc1[j] += qf.y * kv[j];
        }
    }

    float c0 = m0 - g_diag[bh * NPIX + n];
    float c1 = m0 - g_diag[bh * NPIX + n + 1];
    __half out0[8], out1[8];
#pragma unroll
    for (int j = 0; j < 8; j++) {
        int e = eg * 8 + j;
        float2 vf = __half22float2(*(const __half2*)(g_kv_h + (size_t)(INNER + h * DH + e) * BP + base));
        out0[j] = __float2half_rn(SCALE_F * acc0[j] + c0 * vf.x);
        out1[j] = __float2half_rn(SCALE_F * acc1[j] + c1 * vf.y);
    }
    __half2* d0 = (__half2*)(g_att_h + base * INNER + h * DH + eg * 8);
    __half2* d1 = (__half2*)(g_att_h + (base + 1) * INNER + h * DH + eg * 8);
#pragma unroll
    for (int j = 0; j < 4; j++) {
        d0[j] = __halves2half2(out0[j*2], out0[j*2+1]);
        d1[j] = __halves2half2(out1[j*2], out1[j*2+1]);
    }
}

// ---------------------------------------------------------------------------
// Launch
// ---------------------------------------------------------------------------
extern "C" void kernel_launch(void* const* d_in, const int* in_sizes, int n_in,
                              void* d_out, int out_size)
{
    const float* x       = (const float*)d_in[0];
    const float* wq_dw   = (const float*)d_in[1];
    const float* wq_g    = (const float*)d_in[2];
    const float* wq_b    = (const float*)d_in[3];
    const float* wq_m    = (const float*)d_in[4];
    const float* wq_v    = (const float*)d_in[5];
    const float* wq_pw   = (const float*)d_in[6];
    const float* wkv_dw  = (const float*)d_in[7];
    const float* wkv_g   = (const float*)d_in[8];
    const float* wkv_b   = (const float*)d_in[9];
    const float* wkv_m   = (const float*)d_in[10];
    const float* wkv_v   = (const float*)d_in[11];
    const float* wkv_pw  = (const float*)d_in[12];
    const float* wo      = (const float*)d_in[13];
    const float* bo      = (const float*)d_in[14];
    float* out = (float*)d_out;

    cudaFuncSetAttribute(gemm_qkv, cudaFuncAttributeMaxDynamicSharedMemorySize, SMEM_GEMM_BYTES);
    cudaFuncSetAttribute(gemm_out, cudaFuncAttributeMaxDynamicSharedMemorySize, SMEM_GEMM_BYTES);

    // 0) weight conversion to fp16
    cvt_weights_kernel<<<(NW1 + NW2 + NW3 + 255) / 256, 256>>>(wq_pw, wkv_pw, wo);

    // 1) depthwise conv + BN (pixel-pair, transposed [n][c] fp16 output)
    dwconv_bn_kernel<<<dim3(49, 12, 8), 256>>>(
        x, wq_dw, wq_g, wq_b, wq_m, wq_v,
           wkv_dw, wkv_g, wkv_b, wkv_m, wkv_v);

    // 2) q + kv projections, single tensor-core launch (K-tile 64)
    gemm_qkv<<<dim3(196, 12), 256, SMEM_GEMM_BYTES>>>();

    // 3) attention middle
    diag_kernel<<<(NBH * NPIX / 2) / 256, 256>>>();
    reduce_diag2<<<1, 256>>>();
    ktv_partial<<<dim3(NSPLIT, NBH), 128>>>();
    ktv_reduce<<<(NBH * DH * DH) / 256, 256>>>();
    att_out_kernel<<<dim3(NPIX / 64, NBH), 256>>>();

    // 4) output projection (+bias, NCHW scatter)
    gemm_out<<<dim3(196, 3), 256, SMEM_GEMM_BYTES>>>(out, bo);
}

// round 16
// speedup vs baseline: 1.7535x; 1.0469x over previous
#include <cuda_runtime.h>
#include <cuda_fp16.h>
#include <cstdint>

// Problem constants
#define BATCH   8
#define CIN     384
#define NPIX    3136           // 56*56
#define WWID    56
#define BP      25088          // BATCH*NPIX
#define INNER   512
#define KVOUT   1024
#define HEADS   8
#define DH      64
#define NBH     64
#define SCALE_F 0.125f
#define EPS_F   1e-5f
#define NSPLIT  14

// ---------------------------------------------------------------------------
// Scratch (device globals)
// ---------------------------------------------------------------------------
__device__ __align__(16) __half g_yq_h [(size_t)BP * CIN];   // dwconv out, q path  [n][c]
__device__ __align__(16) __half g_ykv_h[(size_t)BP * CIN];   // dwconv out, kv path [n][c]
__device__ __align__(16) __half g_q_h [(size_t)INNER * BP];  // q   [m][n] fp16
__device__ __align__(16) __half g_kv_h[(size_t)KVOUT * BP];  // k|v [m][n] fp16
__device__ __align__(16) __half g_att_h[(size_t)BP * INNER]; // attention out [n][o]
__device__ __align__(16) __half g_wq_h [INNER * CIN];        // fp16 weights
__device__ __align__(16) __half g_wkv_h[KVOUT * CIN];
__device__ __align__(16) __half g_wo_h [CIN * INNER];
__device__ float g_diag[NBH * NPIX];
__device__ float g_ktvp[NSPLIT * NBH * DH * DH];
__device__ float g_ktv [NBH * DH * DH];
__device__ float g_red[512];
__device__ float g_m0[1];

// ---------------------------------------------------------------------------
// Helpers
// ---------------------------------------------------------------------------
__device__ __forceinline__ uint32_t smem_u32(const void* p) {
    uint32_t a;
    asm("{ .reg .u64 t; cvta.to.shared.u64 t, %1; cvt.u32.u64 %0, t; }" : "=r"(a) : "l"(p));
    return a;
}
__device__ __forceinline__ void cp_async16(uint32_t dst, const void* src) {
    asm volatile("cp.async.cg.shared.global [%0], [%1], 16;" :: "r"(dst), "l"(src));
}
#define CP_COMMIT() asm volatile("cp.async.commit_group;" ::: "memory")
#define CP_WAIT(N)  asm volatile("cp.async.wait_group %0;" :: "n"(N) : "memory")

__device__ __forceinline__ void mma_f16(float* c, const uint32_t* a, const uint32_t* b) {
    asm volatile(
        "mma.sync.aligned.m16n8k16.row.col.f32.f16.f16.f32 "
        "{%0,%1,%2,%3}, {%4,%5,%6,%7}, {%8,%9}, {%0,%1,%2,%3};"
        : "+f"(c[0]), "+f"(c[1]), "+f"(c[2]), "+f"(c[3])
        : "r"(a[0]), "r"(a[1]), "r"(a[2]), "r"(a[3]), "r"(b[0]), "r"(b[1]));
}
__device__ __forceinline__ void ldsm_x4(uint32_t& r0, uint32_t& r1, uint32_t& r2, uint32_t& r3,
                                        uint32_t addr) {
    asm volatile("ldmatrix.sync.aligned.m8n8.x4.shared.b16 {%0,%1,%2,%3}, [%4];"
                 : "=r"(r0), "=r"(r1), "=r"(r2), "=r"(r3) : "r"(addr));
}

// ---------------------------------------------------------------------------
// 0) Weight conversion (fp32 -> fp16), all three weights in one launch
// ---------------------------------------------------------------------------
#define NW1 (INNER * CIN)
#define NW2 (KVOUT * CIN)
#define NW3 (CIN * INNER)
__global__ void cvt_weights_kernel(const float* __restrict__ s1, const float* __restrict__ s2,
                                   const float* __restrict__ s3)
{
    int i = blockIdx.x * 256 + threadIdx.x;
    if (i < NW1) {
        g_wq_h[i] = __float2half_rn(s1[i]);
    } else if (i < NW1 + NW2) {
        g_wkv_h[i - NW1] = __float2half_rn(s2[i - NW1]);
    } else if (i < NW1 + NW2 + NW3) {
        g_wo_h[i - NW1 - NW2] = __float2half_rn(s3[i - NW1 - NW2]);
    }
}

// ---------------------------------------------------------------------------
// 1) Depthwise 3x3 conv + BN, output TRANSPOSED [n][c] fp16.
//    Each thread computes 4 adjacent pixels x 2 channels.
//    Row window w-1..w+4 = aligned float4 + 2 scalars.
// ---------------------------------------------------------------------------
__global__ void dwconv_bn_kernel(
    const float* __restrict__ x,
    const float* __restrict__ w1, const float* __restrict__ g1, const float* __restrict__ b1,
    const float* __restrict__ m1, const float* __restrict__ v1,
    const float* __restrict__ w2, const float* __restrict__ g2, const float* __restrict__ b2,
    const float* __restrict__ m2, const float* __restrict__ v2)
{
    __shared__ float s1[32][65];
    __shared__ float s2[32][65];
    int b  = blockIdx.z;
    int ct = blockIdx.y;     // 12 channel tiles of 32
    int pt = blockIdx.x;     // 49 pixel tiles of 64
    int tid = threadIdx.x;
    int quad  = tid & 15;    // pixel quad 0..15 (4 pixels each)
    int c_sub = tid >> 4;    // 0..15
    int p = pt * 64 + quad * 4;
    int h = p / WWID, w = p % WWID;  // 4 | 56 -> quad within one row

#pragma unroll
    for (int i = 0; i < 2; i++) {
        int c_loc = i * 16 + c_sub;
        int c = ct * 32 + c_loc;
        const float* xb = x + ((size_t)(b * CIN + c)) * NPIX;
        const float* wp1 = w1 + c * 9;
        const float* wp2 = w2 + c * 9;
        float a1[4] = {0.f, 0.f, 0.f, 0.f};
        float a2[4] = {0.f, 0.f, 0.f, 0.f};
#pragma unroll
        for (int kh = 0; kh < 3; kh++) {
            int hh = h + kh - 1;
            if (hh < 0 || hh >= WWID) continue;
            const float* row = xb + hh * WWID;
            float xv[6];
            xv[0] = (w > 0) ? row[w - 1] : 0.f;
            float4 mid = *(const float4*)(row + w);        // 16B-aligned
            xv[1] = mid.x; xv[2] = mid.y; xv[3] = mid.z; xv[4] = mid.w;
            xv[5] = (w + 4 < WWID) ? row[w + 4] : 0.f;
            float c10 = wp1[kh * 3 + 0], c11 = wp1[kh * 3 + 1], c12 = wp1[kh * 3 + 2];
            float c20 = wp2[kh * 3 + 0], c21 = wp2[kh * 3 + 1], c22 = wp2[kh * 3 + 2];
#pragma unroll
            for (int j = 0; j < 4; j++) {
                a1[j] += xv[j] * c10 + xv[j+1] * c11 + xv[j+2] * c12;
                a2[j] += xv[j] * c20 + xv[j+1] * c21 + xv[j+2] * c22;
            }
        }
        float inv1 = g1[c] * rsqrtf(v1[c] + EPS_F);
        float inv2 = g2[c] * rsqrtf(v2[c] + EPS_F);
        float ad1 = b1[c] - m1[c] * inv1;
        float ad2 = b2[c] - m2[c] * inv2;
#pragma unroll
        for (int j = 0; j < 4; j++) {
            s1[c_loc][quad * 4 + j] = a1[j] * inv1 + ad1;
            s2[c_loc][quad * 4 + j] = a2[j] * inv2 + ad2;
        }
    }
    __syncthreads();

#pragma unroll
    for (int i = 0; i < 2; i++) {
        int idx = tid + i * 256;
        int pp  = idx >> 3;
        int cq  = idx & 7;
        size_t base = ((size_t)(b * NPIX + pt * 64 + pp)) * CIN + ct * 32 + cq * 4;
        __half2 q0 = __floats2half2_rn(s1[cq*4+0][pp], s1[cq*4+1][pp]);
        __half2 q1 = __floats2half2_rn(s1[cq*4+2][pp], s1[cq*4+3][pp]);
        __half2 k0 = __floats2half2_rn(s2[cq*4+0][pp], s2[cq*4+1][pp]);
        __half2 k1 = __floats2half2_rn(s2[cq*4+2][pp], s2[cq*4+3][pp]);
        *(__half2*)(g_yq_h  + base)     = q0;
        *(__half2*)(g_yq_h  + base + 2) = q1;
        *(__half2*)(g_ykv_h + base)     = k0;
        *(__half2*)(g_ykv_h + base + 2) = k1;
    }
}

// ---------------------------------------------------------------------------
// 2) fp16 mma.sync GEMM body, 3-stage cp.async pipeline, ldmatrix fragments.
//    K-tile 64 halves. C[m][n] = sum_k A[m][k] * B[n][k], fp32 accum.
//    MODE 0: fp16 output to C[m*BP + n].  MODE 1: fp32 NCHW scatter + bias.
// ---------------------------------------------------------------------------
#define KTILE   64
#define SROW_H  72
#define TILE_H  (128 * SROW_H)
#define NSTAGE  3
#define STAGE_BYTES (2 * TILE_H * 2)
#define SMEM_GEMM_BYTES (NSTAGE * STAGE_BYTES)

template<int MODE>
__device__ __forceinline__ void gemm_body(
    __half* smem, const __half* __restrict__ A, const __half* __restrict__ Bm,
    void* __restrict__ Cv, int Kd, const float* __restrict__ bias, int m0, int n0)
{
    int tid = threadIdx.x;
    int wid = tid >> 5;
    int lane = tid & 31;
    int grp = lane >> 2;
    int qid = lane & 3;
    int warp_m = wid & 1;
    int warp_n = wid >> 1;
    int KT = Kd / KTILE;

    uint32_t smem_b = smem_u32(smem);

    auto load_tile = [&](int kt, int stage) {
        int k0 = kt * KTILE;
        uint32_t dA = smem_b + (uint32_t)stage * STAGE_BYTES;
        uint32_t dB = dA + TILE_H * 2;
#pragma unroll
        for (int i = 0; i < 4; i++) {
            int idx = tid + i * 256;
            int row = idx >> 3, q = idx & 7;
            cp_async16(dA + (uint32_t)(row * SROW_H + q * 8) * 2,
                       A + (size_t)(m0 + row) * Kd + k0 + q * 8);
        }
#pragma unroll
        for (int i = 0; i < 4; i++) {
            int idx = tid + i * 256;
            int row = idx >> 3, q = idx & 7;
            cp_async16(dB + (uint32_t)(row * SROW_H + q * 8) * 2,
                       Bm + (size_t)(n0 + row) * Kd + k0 + q * 8);
        }
    };

    float acc[4][4][4];
#pragma unroll
    for (int mt = 0; mt < 4; mt++)
#pragma unroll
        for (int nt = 0; nt < 4; nt++)
#pragma unroll
            for (int r = 0; r < 4; r++) acc[mt][nt][r] = 0.f;

    load_tile(0, 0);
    CP_COMMIT();
    load_tile(1, 1);
    CP_COMMIT();

    int rsel = (lane & 7) + ((lane >> 3) & 1) * 8;
    int csel = (lane >> 4) * 8;

    int stage = 0;
    for (int kt = 0; kt < KT; kt++) {
        CP_WAIT(1);
        __syncthreads();

        uint32_t As_u = smem_b + (uint32_t)stage * STAGE_BYTES;
        uint32_t Bs_u = As_u + TILE_H * 2;

#pragma unroll
        for (int ks = 0; ks < 4; ks++) {
            int col = ks * 16 + csel;
            uint32_t afr[4][4], bfr[4][2];
#pragma unroll
            for (int mt = 0; mt < 4; mt++) {
                uint32_t addr = As_u +
                    (uint32_t)((warp_m * 64 + mt * 16 + rsel) * SROW_H + col) * 2;
                ldsm_x4(afr[mt][0], afr[mt][1], afr[mt][2], afr[mt][3], addr);
            }
#pragma unroll
            for (int p = 0; p < 2; p++) {
                uint32_t addr = Bs_u +
                    (uint32_t)((warp_n * 32 + p * 16 + rsel) * SROW_H + col) * 2;
                uint32_t b0, b1, b2, b3;
                ldsm_x4(b0, b1, b2, b3, addr);
                bfr[p*2  ][0] = b0; bfr[p*2+1][0] = b1;
                bfr[p*2  ][1] = b2; bfr[p*2+1][1] = b3;
            }
#pragma unroll
            for (int mt = 0; mt < 4; mt++)
#pragma unroll
                for (int nt = 0; nt < 4; nt++)
                    mma_f16(acc[mt][nt], afr[mt], bfr[nt]);
        }

        if (kt + 2 < KT) {
            int nstage = stage + 2; if (nstage >= NSTAGE) nstage -= NSTAGE;
            load_tile(kt + 2, nstage);
        }
        CP_COMMIT();
        stage = (stage + 1 == NSTAGE) ? 0 : stage + 1;
    }

    // Epilogue
#pragma unroll
    for (int mt = 0; mt < 4; mt++) {
        int r0 = m0 + warp_m * 64 + mt * 16 + grp;
        int r1 = r0 + 8;
        float bs0 = (MODE == 1) ? bias[r0] : 0.f;
        float bs1 = (MODE == 1) ? bias[r1] : 0.f;
#pragma unroll
        for (int nt = 0; nt < 4; nt++) {
            int n = n0 + warp_n * 32 + nt * 8 + qid * 2;
            float* a4 = acc[mt][nt];
            if (MODE == 0) {
                __half* Ch = (__half*)Cv;
                *(__half2*)(Ch + (size_t)r0 * BP + n) = __floats2half2_rn(a4[0], a4[1]);
                *(__half2*)(Ch + (size_t)r1 * BP + n) = __floats2half2_rn(a4[2], a4[3]);
            } else {
                float* C = (float*)Cv;
                int bb = n / NPIX, p = n - bb * NPIX;
                *(float2*)(C + ((size_t)bb * CIN + r0) * NPIX + p) =
                    make_float2(a4[0] + bs0, a4[1] + bs0);
                *(float2*)(C + ((size_t)bb * CIN + r1) * NPIX + p) =
                    make_float2(a4[2] + bs1, a4[3] + bs1);
            }
        }
    }
}

// Merged q + kv projection: pointer-select, then ONE gemm_body call site.
__global__ void __launch_bounds__(256, 2) gemm_qkv()
{
    extern __shared__ __half smem[];
    int y = blockIdx.y;
    const __half* A;
    const __half* Bm;
    __half* C;
    int m0;
    if (y < 4) { A = g_wq_h;  Bm = g_yq_h;  C = g_q_h;  m0 = y * 128; }
    else       { A = g_wkv_h; Bm = g_ykv_h; C = g_kv_h; m0 = (y - 4) * 128; }
    gemm_body<0>(smem, A, Bm, C, CIN, nullptr, m0, blockIdx.x * 128);
}

// Output projection GEMM (+bias, NCHW scatter)
__global__ void __launch_bounds__(256, 2) gemm_out(float* __restrict__ C,
                                                   const float* __restrict__ bias)
{
    extern __shared__ __half smem[];
    gemm_body<1>(smem, g_wo_h, g_att_h, C, INNER, bias, blockIdx.y * 128, blockIdx.x * 128);
}

// ---------------------------------------------------------------------------
// 3) diag + block partial sum (fused reduce pass 1)
// ---------------------------------------------------------------------------
__global__ void diag_kernel()
{
    __shared__ float sm[256];
    int tid = threadIdx.x;
    int idx = blockIdx.x * 256 + tid;                  // over NBH * NPIX/2
    int n2  = idx % (NPIX / 2);
    int bh  = idx / (NPIX / 2);
    int b = bh >> 3, h = bh & 7;
    int n = n2 * 2;
    size_t base = (size_t)b * NPIX + n;
    float s0 = 0.f, s1 = 0.f;
#pragma unroll 8
    for (int d = 0; d < DH; d++) {
        float2 qf = __half22float2(*(const __half2*)(g_q_h  + (size_t)(h * DH + d) * BP + base));
        float2 kf = __half22float2(*(const __half2*)(g_kv_h + (size_t)(h * DH + d) * BP + base));
        s0 += qf.x * kf.x;
        s1 += qf.y * kf.y;
    }
    s0 *= SCALE_F; s1 *= SCALE_F;
    g_diag[bh * NPIX + n]     = s0;
    g_diag[bh * NPIX + n + 1] = s1;

    sm[tid] = s0 + s1;
    __syncthreads();
    for (int st = 128; st > 0; st >>= 1) {
        if (tid < st) sm[tid] += sm[tid + st];
        __syncthreads();
    }
    if (tid == 0) g_red[blockIdx.x] = sm[0];
}

__global__ void reduce_diag2()
{
    __shared__ float sm[256];
    int tid = threadIdx.x;
    float s = g_red[tid];
    if (tid + 256 < 392) s += g_red[tid + 256];
    sm[tid] = s;
    __syncthreads();
    for (int st = 128; st > 0; st >>= 1) {
        if (tid < st) sm[tid] += sm[tid + st];
        __syncthreads();
    }
    if (tid == 0) g_m0[0] = sm[0];
}

// ---------------------------------------------------------------------------
// 4) ktv partials on tensor cores (grid NSPLIT x 64), fp32 accum
// ---------------------------------------------------------------------------
#define KTV_SROW 40
#define KTV_OP_H (64 * KTV_SROW)

__global__ void __launch_bounds__(128) ktv_partial()
{
    __shared__ __half sK[2 * KTV_OP_H];
    __shared__ __half sV[2 * KTV_OP_H];

    int split = blockIdx.x;
    int bh = blockIdx.y;
    int b = bh >> 3, h = bh & 7;
    int tid = threadIdx.x;
    int wid = tid >> 5;
    int lane = tid & 31;
    int grp = lane >> 2;
    int qid = lane & 3;

    uint32_t sK_u = smem_u32(sK);
    uint32_t sV_u = smem_u32(sV);

    size_t base = (size_t)b * NPIX + split * (NPIX / NSPLIT);
    const __half* Kg = g_kv_h + (size_t)(h * DH) * BP + base;
    const __half* Vg = g_kv_h + (size_t)(INNER + h * DH) * BP + base;

    auto load_chunk = [&](int kt, int s) {
        int n0 = kt * 32;
        uint32_t dK = sK_u + (uint32_t)s * (KTV_OP_H * 2);
        uint32_t dV = sV_u + (uint32_t)s * (KTV_OP_H * 2);
#pragma unroll
        for (int i = 0; i < 2; i++) {
            int idx = tid + i * 128;
            int row = idx >> 2, q = idx & 3;
            cp_async16(dK + (uint32_t)(row * KTV_SROW + q * 8) * 2,
                       Kg + (size_t)row * BP + n0 + q * 8);
        }
#pragma unroll
        for (int i = 0; i < 2; i++) {
            int idx = tid + i * 128;
            int row = idx >> 2, q = idx & 3;
            cp_async16(dV + (uint32_t)(row * KTV_SROW + q * 8) * 2,
                       Vg + (size_t)row * BP + n0 + q * 8);
        }
    };

    float acc[8][4];
#pragma unroll
    for (int nt = 0; nt < 8; nt++)
#pragma unroll
        for (int r = 0; r < 4; r++) acc[nt][r] = 0.f;

    const int KT = (NPIX / NSPLIT) / 32;   // 7
    load_chunk(0, 0);
    CP_COMMIT();

    int rsel = (lane & 7) + ((lane >> 3) & 1) * 8;
    int csel = (lane >> 4) * 8;

    for (int kt = 0; kt < KT; kt++) {
        int buf = kt & 1;
        if (kt + 1 < KT) {
            load_chunk(kt + 1, buf ^ 1);
            CP_COMMIT();
            CP_WAIT(1);
        } else {
            CP_WAIT(0);
        }
        __syncthreads();

        uint32_t Kb = sK_u + (uint32_t)buf * (KTV_OP_H * 2);
        uint32_t Vb = sV_u + (uint32_t)buf * (KTV_OP_H * 2);

#pragma unroll
        for (int ks = 0; ks < 2; ks++) {
            int col = ks * 16 + csel;
            uint32_t afr[4];
            ldsm_x4(afr[0], afr[1], afr[2], afr[3],
                    Kb + (uint32_t)((wid * 16 + rsel) * KTV_SROW + col) * 2);
            uint32_t bfr[8][2];
#pragma unroll
            for (int p = 0; p < 4; p++) {
                uint32_t b0, b1, b2, b3;
                ldsm_x4(b0, b1, b2, b3,
                        Vb + (uint32_t)((p * 16 + rsel) * KTV_SROW + col) * 2);
                bfr[p*2  ][0] = b0; bfr[p*2+1][0] = b1;
                bfr[p*2  ][1] = b2; bfr[p*2+1][1] = b3;
            }
#pragma unroll
            for (int nt = 0; nt < 8; nt++)
                mma_f16(acc[nt], afr, bfr[nt]);
        }
        __syncthreads();
    }

    float* dst = g_ktvp + ((size_t)(split * NBH + bh)) * (DH * DH);
    int d0 = wid * 16 + grp;
    int d1 = d0 + 8;
#pragma unroll
    for (int nt = 0; nt < 8; nt++) {
        int e = nt * 8 + qid * 2;
        *(float2*)(dst + d0 * DH + e) = make_float2(acc[nt][0], acc[nt][1]);
        *(float2*)(dst + d1 * DH + e) = make_float2(acc[nt][2], acc[nt][3]);
    }
}

__global__ void ktv_reduce()
{
    int idx = blockIdx.x * blockDim.x + threadIdx.x;
    if (idx >= NBH * DH * DH) return;
    float s = 0.f;
#pragma unroll
    for (int sp = 0; sp < NSPLIT; sp++)
        s += g_ktvp[(size_t)sp * (NBH * DH * DH) + idx];
    g_ktv[idx] = s;
}

// ---------------------------------------------------------------------------
// 5) att_out: 64 pixels per block, each thread handles 2 pixels x 8 e values.
// ---------------------------------------------------------------------------
__global__ void att_out_kernel()
{
    __shared__ float ktv_s[DH * DH];
    int bh = blockIdx.y;
    int b = bh >> 3, h = bh & 7;

    for (int i = threadIdx.x; i < DH * DH; i += 256)
        ktv_s[i] = g_ktv[bh * (DH * DH) + i];
    __syncthreads();

    float m0 = g_m0[0];
    int pn = threadIdx.x & 31;
    int eg = threadIdx.x >> 5;
    int n = blockIdx.x * 64 + pn * 2;
    size_t base = (size_t)b * NPIX + n;

    float acc0[8], acc1[8];
#pragma unroll
    for (int j = 0; j < 8; j++) { acc0[j] = 0.f; acc1[j] = 0.f; }

#pragma unroll 4
    for (int d = 0; d < DH; d++) {
        float2 qf = __half22float2(*(const __half2*)(g_q_h + (size_t)(h * DH + d) * BP + base));
        const float* kv = ktv_s + d * DH + eg * 8;
#pragma unroll
        for (int j = 0; j < 8; j++) {
            acc0[j] += qf.x * kv[j];
            acc1[j] += qf.y * kv[j];
        }
    }

    float c0 = m0 - g_diag[bh * NPIX + n];
    float c1 = m0 - g_diag[bh * NPIX + n + 1];
    __half out0[8], out1[8];
#pragma unroll
    for (int j = 0; j < 8; j++) {
        int e = eg * 8 + j;
        float2 vf = __half22float2(*(const __half2*)(g_kv_h + (size_t)(INNER + h * DH + e) * BP + base));
        out0[j] = __float2half_rn(SCALE_F * acc0[j] + c0 * vf.x);
        out1[j] = __float2half_rn(SCALE_F * acc1[j] + c1 * vf.y);
    }
    __half2* d0 = (__half2*)(g_att_h + base * INNER + h * DH + eg * 8);
    __half2* d1 = (__half2*)(g_att_h + (base + 1) * INNER + h * DH + eg * 8);
#pragma unroll
    for (int j = 0; j < 4; j++) {
        d0[j] = __halves2half2(out0[j*2], out0[j*2+1]);
        d1[j] = __halves2half2(out1[j*2], out1[j*2+1]);
    }
}

// ---------------------------------------------------------------------------
// Launch
// ---------------------------------------------------------------------------
extern "C" void kernel_launch(void* const* d_in, const int* in_sizes, int n_in,
                              void* d_out, int out_size)
{
    const float* x       = (const float*)d_in[0];
    const float* wq_dw   = (const float*)d_in[1];
    const float* wq_g    = (const float*)d_in[2];
    const float* wq_b    = (const float*)d_in[3];
    const float* wq_m    = (const float*)d_in[4];
    const float* wq_v    = (const float*)d_in[5];
    const float* wq_pw   = (const float*)d_in[6];
    const float* wkv_dw  = (const float*)d_in[7];
    const float* wkv_g   = (const float*)d_in[8];
    const float* wkv_b   = (const float*)d_in[9];
    const float* wkv_m   = (const float*)d_in[10];
    const float* wkv_v   = (const float*)d_in[11];
    const float* wkv_pw  = (const float*)d_in[12];
    const float* wo      = (const float*)d_in[13];
    const float* bo      = (const float*)d_in[14];
    float* out = (float*)d_out;

    cudaFuncSetAttribute(gemm_qkv, cudaFuncAttributeMaxDynamicSharedMemorySize, SMEM_GEMM_BYTES);
    cudaFuncSetAttribute(gemm_out, cudaFuncAttributeMaxDynamicSharedMemorySize, SMEM_GEMM_BYTES);

    // 0) weight conversion to fp16
    cvt_weights_kernel<<<(NW1 + NW2 + NW3 + 255) / 256, 256>>>(wq_pw, wkv_pw, wo);

    // 1) depthwise conv + BN (4-pixel threads, transposed [n][c] fp16 output)
    dwconv_bn_kernel<<<dim3(49, 12, 8), 256>>>(
        x, wq_dw, wq_g, wq_b, wq_m, wq_v,
           wkv_dw, wkv_g, wkv_b, wkv_m, wkv_v);

    // 2) q + kv projections, single tensor-core launch (K-tile 64)
    gemm_qkv<<<dim3(196, 12), 256, SMEM_GEMM_BYTES>>>();

    // 3) attention middle
    diag_kernel<<<(NBH * NPIX / 2) / 256, 256>>>();
    reduce_diag2<<<1, 256>>>();
    ktv_partial<<<dim3(NSPLIT, NBH), 128>>>();
    ktv_reduce<<<(NBH * DH * DH) / 256, 256>>>();
    att_out_kernel<<<dim3(NPIX / 64, NBH), 256>>>();

    // 4) output projection (+bias, NCHW scatter)
    gemm_out<<<dim3(196, 3), 256, SMEM_GEMM_BYTES>>>(out, bo);
}